// round 9
// baseline (speedup 1.0000x reference)
#include <cuda_runtime.h>
#include <cuda_bf16.h>
#include <math.h>
#include <string.h>

#define NN   6144
#define G    24
#define DIN  128
#define DH   64
#define NH   8
#define QKV_W 1536

typedef unsigned long long u64;
typedef unsigned int u32;

// ---------------- device scratch --------------------------------------------
__device__ float g_h[NN * DH];                 // residual-init + attn accum
__device__ unsigned short g_xhi[NN * DIN];
__device__ unsigned short g_xlo[NN * DIN];
__device__ unsigned short g_whi[QKV_W * DIN];
__device__ unsigned short g_wlo[QKV_W * DIN];
__device__ float g_xs_part[96 * DIN];
__device__ float g_xq_part[96 * DIN];
__device__ float g_hsum[DH];
__device__ float g_hsumsq[DH];

// ---------------- PTX helpers -----------------------------------------------
__device__ __forceinline__ u32 smem_u32(const void* p) {
    u32 a;
    asm("{ .reg .u64 t; cvta.to.shared.u64 t, %1; cvt.u32.u64 %0, t; }"
        : "=r"(a) : "l"(p));
    return a;
}
__device__ __forceinline__ void ldsm_x4(u32& r0, u32& r1, u32& r2, u32& r3, u32 addr) {
    asm volatile("ldmatrix.sync.aligned.m8n8.x4.shared.b16 {%0,%1,%2,%3}, [%4];"
                 : "=r"(r0), "=r"(r1), "=r"(r2), "=r"(r3) : "r"(addr));
}
__device__ __forceinline__ void ldsm_x2(u32& r0, u32& r1, u32 addr) {
    asm volatile("ldmatrix.sync.aligned.m8n8.x2.shared.b16 {%0,%1}, [%2];"
                 : "=r"(r0), "=r"(r1) : "r"(addr));
}
__device__ __forceinline__ void mma_bf16(float* d, const u32* a, const u32* b) {
    asm volatile(
        "mma.sync.aligned.m16n8k16.row.col.f32.bf16.bf16.f32 "
        "{%0,%1,%2,%3},{%4,%5,%6,%7},{%8,%9},{%0,%1,%2,%3};"
        : "+f"(d[0]), "+f"(d[1]), "+f"(d[2]), "+f"(d[3])
        : "r"(a[0]), "r"(a[1]), "r"(a[2]), "r"(a[3]), "r"(b[0]), "r"(b[1]));
}

__device__ __forceinline__ unsigned short bf16bits(float v) {
    __nv_bfloat16 b = __float2bfloat16(v);
    unsigned short s; memcpy(&s, &b, 2); return s;
}
__device__ __forceinline__ float bf16val(float v) {
    return __bfloat162float(__float2bfloat16(v));
}

// ---------------- K1: x stats partials --------------------------------------
__global__ void __launch_bounds__(256)
k_xstats(const float* __restrict__ x) {
    __shared__ float smS[8 * 128], smQ[8 * 128];
    int t  = threadIdx.x;
    int c4 = t & 31;
    int rs = t >> 5;
    int r0 = blockIdx.x * 64;

    const float4* xg = (const float4*)x;
    float4 s = make_float4(0.f, 0.f, 0.f, 0.f);
    float4 q = make_float4(0.f, 0.f, 0.f, 0.f);
    #pragma unroll
    for (int r = rs; r < 64; r += 8) {
        float4 v = xg[(size_t)(r0 + r) * 32 + c4];
        s.x += v.x; s.y += v.y; s.z += v.z; s.w += v.w;
        q.x += v.x * v.x; q.y += v.y * v.y; q.z += v.z * v.z; q.w += v.w * v.w;
    }
    ((float4*)smS)[rs * 32 + c4] = s;
    ((float4*)smQ)[rs * 32 + c4] = q;
    __syncthreads();
    if (t < 128) {
        float ss = 0.f, qq = 0.f;
        #pragma unroll
        for (int j = 0; j < 8; j++) { ss += smS[j * 128 + t]; qq += smQ[j * 128 + t]; }
        g_xs_part[blockIdx.x * 128 + t] = ss;
        g_xq_part[blockIdx.x * 128 + t] = qq;
    }
}

// ---------------- K2: normalize x -> bf16 hi/lo; W -> bf16 hi/lo; h init ----
__global__ void __launch_bounds__(256)
k_xnorm(const float* __restrict__ x,
        const float* __restrict__ nq_w, const float* __restrict__ nq_b,
        const float* __restrict__ nq_ms,
        const float* __restrict__ wq, const float* __restrict__ wk,
        const float* __restrict__ wv) {
    int tid = threadIdx.x;
    int b   = blockIdx.x;

    if (b == 0 && tid < DH) { g_hsum[tid] = 0.f; g_hsumsq[tid] = 0.f; }

    uint2* xh = (uint2*)g_xhi;
    uint2* xl = (uint2*)g_xlo;
    uint2* wh = (uint2*)g_whi;
    uint2* wl = (uint2*)g_wlo;

    if (b < 48) {
        __shared__ float As[128], Bs[128];
        if (tid < 128) {
            float ss = 0.f, qq = 0.f;
            #pragma unroll 8
            for (int p = 0; p < 96; p++) {
                ss += g_xs_part[p * 128 + tid];
                qq += g_xq_part[p * 128 + tid];
            }
            const float invN = 1.0f / NN;
            float mean = ss * invN;
            float ex2  = qq * invN;
            float mm   = mean * nq_ms[tid];
            float var  = ex2 - 2.f * mm * mean + mm * mm;
            float rinv = rsqrtf(var + 1e-5f);
            As[tid] = nq_w[tid] * rinv;
            Bs[tid] = nq_b[tid] - nq_w[tid] * rinv * mm;
        }
        __syncthreads();
        int r0 = b * 128;
        const float4* xg = (const float4*)x;
        for (int i = tid; i < 128 * 32; i += 256) {
            int row = i >> 5, c4 = i & 31, c = c4 * 4;
            float4 v = xg[(size_t)(r0 + row) * 32 + c4];
            float f[4];
            f[0] = fmaf(v.x, As[c],     Bs[c]);
            f[1] = fmaf(v.y, As[c + 1], Bs[c + 1]);
            f[2] = fmaf(v.z, As[c + 2], Bs[c + 2]);
            f[3] = fmaf(v.w, As[c + 3], Bs[c + 3]);
            unsigned short h[4], l[4];
            #pragma unroll
            for (int j = 0; j < 4; j++) {
                h[j] = bf16bits(f[j]);
                l[j] = bf16bits(f[j] - bf16val(f[j]));
            }
            uint2 uh, ul;
            uh.x = (u32)h[0] | ((u32)h[1] << 16); uh.y = (u32)h[2] | ((u32)h[3] << 16);
            ul.x = (u32)l[0] | ((u32)l[1] << 16); ul.y = (u32)l[2] | ((u32)l[3] << 16);
            size_t idx = (size_t)(r0 + row) * 32 + c4;
            xh[idx] = uh; xl[idx] = ul;
        }
        // residual init: g_h = x[:, :64] + x[:, 64:]
        float4* h4 = (float4*)g_h;
        for (int i = tid; i < 128 * 16; i += 256) {
            int row = i >> 4, c4 = i & 15;
            float4 xa = xg[(size_t)(r0 + row) * 32 + c4];
            float4 xb = xg[(size_t)(r0 + row) * 32 + 16 + c4];
            h4[(size_t)(r0 + row) * 16 + c4] =
                make_float4(xa.x + xb.x, xa.y + xb.y, xa.z + xb.z, xa.w + xb.w);
        }
    } else {
        int wr0 = (b - 48) * 128;
        for (int i = tid; i < 128 * 32; i += 256) {
            int row = i >> 5, c4 = i & 31;
            int gidx = wr0 + row;
            int mat = gidx >> 9, lr = gidx & 511;
            const float4* src = (const float4*)(mat == 0 ? wq : (mat == 1 ? wk : wv));
            float4 v = src[(size_t)lr * 32 + c4];
            float f[4] = {v.x, v.y, v.z, v.w};
            unsigned short h[4], l[4];
            #pragma unroll
            for (int j = 0; j < 4; j++) {
                h[j] = bf16bits(f[j]);
                l[j] = bf16bits(f[j] - bf16val(f[j]));
            }
            uint2 uh, ul;
            uh.x = (u32)h[0] | ((u32)h[1] << 16); uh.y = (u32)h[2] | ((u32)h[3] << 16);
            ul.x = (u32)l[0] | ((u32)l[1] << 16); ul.y = (u32)l[2] | ((u32)l[3] << 16);
            size_t idx = (size_t)gidx * 32 + c4;
            wh[idx] = uh; wl[idx] = ul;
        }
    }
}

// ---------------- K3: FUSED qkv-GEMM + attention ----------------------------
// CTA = (group of 4 sets = 96 nodes) x (head). grid 512, 256 threads.
#define ROWB 272                 // bytes per bf16 smem row (136 bf16)
#define ATILE (96 * ROWB)        // 26112
#define BTILE (64 * ROWB)        // 17408
#define QSF   (96 * 68)          // fp32 Q/V smem floats (pitch 68 = 17 f4)
#define OFF_BIAS 0
#define OFF_AH   512
#define OFF_AL   (OFF_AH + ATILE)
#define OFF_BH   (OFF_AL + ATILE)
#define OFF_BL   (OFF_BH + BTILE)
#define OFF_QS   (OFF_BL + BTILE)
#define OFF_VS   (OFF_QS + QSF * 4)
#define OFF_KT   (OFF_VS + QSF * 4)        // 4 sets * 400 float4 = 25600 B
#define OFF_AL2  (OFF_KT + 25600)          // alpha: 4*576 floats = 9216 B
#define SMEM_FUSED (OFF_AL2 + 9216)        // 174,592 B

__global__ void __launch_bounds__(256, 1)
k_fused(const float* __restrict__ bq, const float* __restrict__ bk,
        const float* __restrict__ bv) {
    extern __shared__ char smc[];
    float*  bias_s = (float*)(smc + OFF_BIAS);
    char*   aH = smc + OFF_AH;
    char*   aL = smc + OFF_AL;
    char*   bH = smc + OFF_BH;
    char*   bL = smc + OFF_BL;
    float*  qs = (float*)(smc + OFF_QS);     // Q fp32 [96][68]
    float*  vs = (float*)(smc + OFF_VS);     // V fp32 [96][68] (also K temp)
    float4* kt4 = (float4*)(smc + OFF_KT);   // K^T [set][c4(16)][25]
    float*  alpha = (float*)(smc + OFF_AL2); // [set][24][24]

    int tid = threadIdx.x;
    int head  = blockIdx.x & 7;
    int group = blockIdx.x >> 3;
    int grow0 = group * 96;

    const uint2* xh = (const uint2*)g_xhi;
    const uint2* xl = (const uint2*)g_xlo;
    const uint2* wh = (const uint2*)g_whi;
    const uint2* wl = (const uint2*)g_wlo;

    // ---- load A tile (96 rows of normalized x, bf16 hi/lo) ----
    #pragma unroll
    for (int i = tid; i < 96 * 32; i += 256) {
        int row = i >> 5, c4 = i & 31;
        int so = row * ROWB + c4 * 8;
        size_t ax = (size_t)(grow0 + row) * 32 + c4;
        *(uint2*)(aH + so) = xh[ax];
        *(uint2*)(aL + so) = xl[ax];
    }

    u32 sb = smem_u32(smc);
    u32 aHb = sb + OFF_AH, aLb = sb + OFF_AL;
    u32 bHb = sb + OFF_BH, bLb = sb + OFF_BL;

    int t   = tid & 31;
    int wid = tid >> 5;
    int wm = (wid & 1) * 48;             // warp M offset: {0, 48}
    int wn = (wid >> 1) * 16;            // warp N offset: {0,16,32,48}
    int rowA = ((t >> 3) & 1) * 8 + (t & 7);
    int kofA = (t >> 4) * 8;
    int rowB = (t & 7);
    int kofB = ((t >> 3) & 1) * 8;
    int tq = t >> 2, tr = t & 3;

    // three GEMM stages: 0=Q, 1=K(into vs temp), 2=V
    #pragma unroll 1
    for (int stage = 0; stage < 3; stage++) {
        int wrow0 = stage * 512 + head * 64;
        const float* bias = stage == 0 ? bq : (stage == 1 ? bk : bv);
        if (tid < 64) bias_s[tid] = bias[head * 64 + tid];
        #pragma unroll
        for (int i = tid; i < 64 * 32; i += 256) {
            int row = i >> 5, c4 = i & 31;
            int so = row * ROWB + c4 * 8;
            size_t bx = (size_t)(wrow0 + row) * 32 + c4;
            *(uint2*)(bH + so) = wh[bx];
            *(uint2*)(bL + so) = wl[bx];
        }
        __syncthreads();

        float acc[3][2][4];
        #pragma unroll
        for (int mf = 0; mf < 3; mf++)
            #pragma unroll
            for (int nf = 0; nf < 2; nf++)
                #pragma unroll
                for (int j = 0; j < 4; j++) acc[mf][nf][j] = 0.f;

        for (int k = 0; k < 128; k += 16) {
            u32 ah[3][4], al[3][4], bh2[2][2], bl2[2][2];
            #pragma unroll
            for (int mf = 0; mf < 3; mf++) {
                u32 off = (u32)((wm + mf * 16 + rowA) * ROWB + (k + kofA) * 2);
                ldsm_x4(ah[mf][0], ah[mf][1], ah[mf][2], ah[mf][3], aHb + off);
                ldsm_x4(al[mf][0], al[mf][1], al[mf][2], al[mf][3], aLb + off);
            }
            #pragma unroll
            for (int nf = 0; nf < 2; nf++) {
                u32 off = (u32)((wn + nf * 8 + rowB) * ROWB + (k + kofB) * 2);
                ldsm_x2(bh2[nf][0], bh2[nf][1], bHb + off);
                ldsm_x2(bl2[nf][0], bl2[nf][1], bLb + off);
            }
            #pragma unroll
            for (int mf = 0; mf < 3; mf++)
                #pragma unroll
                for (int nf = 0; nf < 2; nf++) {
                    mma_bf16(acc[mf][nf], ah[mf], bh2[nf]);
                    mma_bf16(acc[mf][nf], ah[mf], bl2[nf]);
                    mma_bf16(acc[mf][nf], al[mf], bh2[nf]);
                }
        }

        // epilogue: write fp32 + bias into smem (Q -> qs, K -> vs temp, V -> vs)
        float* dstbuf = (stage == 0) ? qs : vs;
        #pragma unroll
        for (int mf = 0; mf < 3; mf++) {
            int m = wm + mf * 16 + tq;
            #pragma unroll
            for (int nf = 0; nf < 2; nf++) {
                int ln = wn + nf * 8 + tr * 2;
                float b0 = bias_s[ln], b1 = bias_s[ln + 1];
                *(float2*)(dstbuf + m * 68 + ln) =
                    make_float2(acc[mf][nf][0] + b0, acc[mf][nf][1] + b1);
                *(float2*)(dstbuf + (m + 8) * 68 + ln) =
                    make_float2(acc[mf][nf][2] + b0, acc[mf][nf][3] + b1);
            }
        }
        __syncthreads();

        if (stage == 1) {
            // transpose K (vs temp, row-major) -> kt4 [set][c4][25]
            #pragma unroll
            for (int i = tid; i < 4 * 24 * 16; i += 256) {
                int set = i / 384, r = i - set * 384;
                int n = r >> 4, c4 = r & 15;
                kt4[set * 400 + c4 * 25 + n] =
                    *(float4*)(vs + (set * 24 + n) * 68 + c4 * 4);
            }
            __syncthreads();
        }
    }

    // ---- logits: 4 sets x 12 d-pairs x 8 sg (2 d x 3 s per thread) ----
    for (int idx = tid; idx < 4 * 96; idx += 256) {
        int set = idx / 96, r = idx - set * 96;
        int d0 = (r >> 3) * 2;          // 0,2,...,22
        int sg = r & 7;
        const float4* q4 = (const float4*)qs;
        float a00 = 0.f, a01 = 0.f, a02 = 0.f;
        float a10 = 0.f, a11 = 0.f, a12 = 0.f;
        #pragma unroll
        for (int j = 0; j < 16; j++) {
            float4 q0 = q4[(set * 24 + d0) * 17 + j];
            float4 q1 = q4[(set * 24 + d0 + 1) * 17 + j];
            const float4* kp = &kt4[set * 400 + j * 25 + sg * 3];
            float4 k0 = kp[0], k1 = kp[1], k2 = kp[2];
            a00 += q0.x * k0.x + q0.y * k0.y + q0.z * k0.z + q0.w * k0.w;
            a01 += q0.x * k1.x + q0.y * k1.y + q0.z * k1.z + q0.w * k1.w;
            a02 += q0.x * k2.x + q0.y * k2.y + q0.z * k2.z + q0.w * k2.w;
            a10 += q1.x * k0.x + q1.y * k0.y + q1.z * k0.z + q1.w * k0.w;
            a11 += q1.x * k1.x + q1.y * k1.y + q1.z * k1.z + q1.w * k1.w;
            a12 += q1.x * k2.x + q1.y * k2.y + q1.z * k2.z + q1.w * k2.w;
        }
        float* r0 = alpha + set * 576 + d0 * G + sg * 3;
        float* r1 = r0 + G;
        r0[0] = a00 * 0.125f; r0[1] = a01 * 0.125f; r0[2] = a02 * 0.125f;
        r1[0] = a10 * 0.125f; r1[1] = a11 * 0.125f; r1[2] = a12 * 0.125f;
    }
    __syncthreads();

    // ---- softmax per (set, d): 96 rows ----
    if (tid < 96) {
        int set = tid / 24, d = tid - set * 24;
        float* row = alpha + set * 576 + d * G;
        float m = row[0];
        #pragma unroll
        for (int s = 1; s < G; s++) m = fmaxf(m, row[s]);
        float sum = 0.f;
        #pragma unroll
        for (int s = 0; s < G; s++) {
            float e = expf(row[s] - m);
            row[s] = e;
            sum += e;
        }
        float inv = 1.0f / (sum + 1e-16f);
        #pragma unroll
        for (int s = 0; s < G; s++) row[s] *= inv;
    }
    __syncthreads();

    // ---- aggregate + atomicAdd into g_h ----
    for (int idx = tid; idx < 4 * 192; idx += 256) {
        int set = idx / 192, r = idx - set * 192;
        int d  = r >> 3;
        int cc = r & 7;
        const float4* v4 = (const float4*)vs;
        float4 acc0 = make_float4(0.f, 0.f, 0.f, 0.f);
        float4 acc1 = make_float4(0.f, 0.f, 0.f, 0.f);
        const float* ar = alpha + set * 576 + d * G;
        #pragma unroll
        for (int s = 0; s < G; s++) {
            float a = ar[s];
            float4 v0 = v4[(set * 24 + s) * 17 + cc];
            float4 v1 = v4[(set * 24 + s) * 17 + cc + 8];
            acc0.x = fmaf(a, v0.x, acc0.x); acc0.y = fmaf(a, v0.y, acc0.y);
            acc0.z = fmaf(a, v0.z, acc0.z); acc0.w = fmaf(a, v0.w, acc0.w);
            acc1.x = fmaf(a, v1.x, acc1.x); acc1.y = fmaf(a, v1.y, acc1.y);
            acc1.z = fmaf(a, v1.z, acc1.z); acc1.w = fmaf(a, v1.w, acc1.w);
        }
        float* dst = g_h + (size_t)(grow0 + set * 24 + d) * DH;
        atomicAdd(dst + cc * 4 + 0, acc0.x * 0.125f);
        atomicAdd(dst + cc * 4 + 1, acc0.y * 0.125f);
        atomicAdd(dst + cc * 4 + 2, acc0.z * 0.125f);
        atomicAdd(dst + cc * 4 + 3, acc0.w * 0.125f);
        atomicAdd(dst + 32 + cc * 4 + 0, acc1.x * 0.125f);
        atomicAdd(dst + 32 + cc * 4 + 1, acc1.y * 0.125f);
        atomicAdd(dst + 32 + cc * 4 + 2, acc1.z * 0.125f);
        atomicAdd(dst + 32 + cc * 4 + 3, acc1.w * 0.125f);
    }
}

// ---------------- K4: h stats (reads finished g_h, 1.57MB) ------------------
__global__ void __launch_bounds__(256)
k_hstats() {
    __shared__ float smS[16 * 64], smQ[16 * 64];
    int t  = threadIdx.x;
    int c4 = t & 15;
    int rs = t >> 4;
    int r0 = blockIdx.x * 512;

    const float4* h4 = (const float4*)g_h;
    float4 s = make_float4(0.f, 0.f, 0.f, 0.f);
    float4 q = make_float4(0.f, 0.f, 0.f, 0.f);
    #pragma unroll 4
    for (int r = rs; r < 512; r += 16) {
        float4 a = h4[(size_t)(r0 + r) * 16 + c4];
        s.x += a.x; s.y += a.y; s.z += a.z; s.w += a.w;
        q.x += a.x * a.x; q.y += a.y * a.y; q.z += a.z * a.z; q.w += a.w * a.w;
    }
    ((float4*)smS)[rs * 16 + c4] = s;
    ((float4*)smQ)[rs * 16 + c4] = q;
    __syncthreads();
    if (t < 64) {
        float ss = 0.f, qq = 0.f;
        #pragma unroll
        for (int j = 0; j < 16; j++) { ss += smS[j * 64 + t]; qq += smQ[j * 64 + t]; }
        atomicAdd(&g_hsum[t], ss);
        atomicAdd(&g_hsumsq[t], qq);
    }
}

__device__ __forceinline__ float gelu_exact(float v) {
    return 0.5f * v * (1.0f + erff(v * 0.70710678118654752f));
}

// ---------------- K5: global norm + PFF + per-set norm + score + pooling ----
#define WP 65
__global__ void __launch_bounds__(256)
k_final(const float* __restrict__ x,
        const float* __restrict__ no_w, const float* __restrict__ no_b,
        const float* __restrict__ no_ms,
        const float* __restrict__ o_w1, const float* __restrict__ o_b1,
        const float* __restrict__ o_w2, const float* __restrict__ o_b2,
        const float* __restrict__ pn_w, const float* __restrict__ pn_b,
        const float* __restrict__ pn_ms,
        const float* __restrict__ p_w1, const float* __restrict__ p_b1,
        const float* __restrict__ p_w2, const float* __restrict__ p_b2,
        float* __restrict__ out) {
    extern __shared__ float dsm[];
    float* w1T  = dsm;
    float* w2T  = w1T + 64 * WP;
    float* pw1T = w2T + 64 * WP;
    float* hs   = pw1T + 64 * WP;
    float* hn   = hs + G * DH;
    float* t1   = hn + G * DH;
    float* h2   = t1 + G * DH;
    float* a2   = h2 + G * DH;
    float* b2   = a2 + DH;
    float* cm   = b2 + DH;
    float* cr   = cm + DH;
    float* b1s  = cr + DH;
    float* b2s  = b1s + DH;
    float* pb1s = b2s + DH;
    float* pw2s = pb1s + DH;
    float* score = pw2s + DH;
    float* wsf   = score + G;

    int tid = threadIdx.x;
    int n0  = blockIdx.x * G;

    for (int i = tid; i < 64 * 64; i += 256) {
        int j = i >> 6, c = i & 63;
        w1T[c * WP + j]  = o_w1[i];
        w2T[c * WP + j]  = o_w2[i];
        pw1T[c * WP + j] = p_w1[i];
    }
    if (tid < DH) {
        b1s[tid] = o_b1[tid]; b2s[tid] = o_b2[tid];
        pb1s[tid] = p_b1[tid]; pw2s[tid] = p_w2[tid];
        const float invN = 1.0f / NN;
        float mean = g_hsum[tid] * invN;
        float ex2  = g_hsumsq[tid] * invN;
        float mm   = mean * no_ms[tid];
        float var  = ex2 - 2.f * mm * mean + mm * mm;
        float rinv = rsqrtf(var + 1e-5f);
        a2[tid] = no_w[tid] * rinv;
        b2[tid] = no_b[tid] - no_w[tid] * rinv * mm;
    }
    for (int i = tid; i < G * DH; i += 256) hs[i] = g_h[(size_t)n0 * DH + i];
    __syncthreads();

    for (int i = tid; i < G * DH; i += 256) {
        int c = i & 63;
        hn[i] = fmaf(hs[i], a2[c], b2[c]);
    }
    __syncthreads();

    for (int i = tid; i < G * DH; i += 256) {
        int d = i >> 6, j = i & 63;
        float acc = b1s[j];
        const float* hr = hn + d * DH;
        #pragma unroll 16
        for (int c = 0; c < DH; c++) acc = fmaf(hr[c], w1T[c * WP + j], acc);
        t1[i] = gelu_exact(acc);
    }
    __syncthreads();

    for (int i = tid; i < G * DH; i += 256) {
        int d = i >> 6, c = i & 63;
        float acc = b2s[c];
        const float* tr = t1 + d * DH;
        #pragma unroll 16
        for (int j = 0; j < DH; j++) acc = fmaf(tr[j], w2T[j * WP + c], acc);
        h2[i] = hs[i] + acc;
    }
    __syncthreads();

    if (tid < DH) {
        int c = tid;
        float m = 0.f;
        #pragma unroll
        for (int d = 0; d < G; d++) m += h2[d * DH + c];
        m *= (1.0f / G);
        float mm = m * pn_ms[c];
        float vv = 0.f;
        #pragma unroll
        for (int d = 0; d < G; d++) { float t = h2[d * DH + c] - mm; vv += t * t; }
        vv *= (1.0f / G);
        cm[c] = mm;
        cr[c] = pn_w[c] * rsqrtf(vv + 1e-5f);
    }
    __syncthreads();

    for (int i = tid; i < G * DH; i += 256) {
        int c = i & 63;
        hn[i] = fmaf(h2[i] - cm[c], cr[c], pn_b[c]);
    }
    __syncthreads();

    for (int i = tid; i < G * DH; i += 256) {
        int d = i >> 6, j = i & 63;
        float acc = pb1s[j];
        const float* hr = hn + d * DH;
        #pragma unroll 16
        for (int c = 0; c < DH; c++) acc = fmaf(hr[c], pw1T[c * WP + j], acc);
        t1[i] = gelu_exact(acc);
    }
    __syncthreads();

    if (tid < G) {
        float acc = p_b2[0];
        const float* tr = t1 + tid * DH;
        #pragma unroll 16
        for (int j = 0; j < DH; j++) acc = fmaf(tr[j], pw2s[j], acc);
        score[tid] = acc;
    }
    __syncthreads();

    if (tid == 0) {
        float m = score[0];
        #pragma unroll
        for (int d = 1; d < G; d++) m = fmaxf(m, score[d]);
        float sum = 0.f;
        #pragma unroll
        for (int d = 0; d < G; d++) { wsf[d] = expf(score[d] - m); sum += wsf[d]; }
        float inv = 1.0f / (sum + 1e-16f);
        #pragma unroll
        for (int d = 0; d < G; d++) wsf[d] *= inv;
    }
    __syncthreads();

    if (tid < DIN) {
        float acc = 0.f;
        #pragma unroll
        for (int d = 0; d < G; d++)
            acc = fmaf(wsf[d], x[(size_t)(n0 + d) * DIN + tid], acc);
        out[blockIdx.x * DIN + tid] = acc;
    }
}

// ---------------- launch -----------------------------------------------------
extern "C" void kernel_launch(void* const* d_in, const int* in_sizes, int n_in,
                              void* d_out, int out_size) {
    const float* x     = (const float*)d_in[0];
    const float* nq_w  = (const float*)d_in[4];
    const float* nq_b  = (const float*)d_in[5];
    const float* nq_ms = (const float*)d_in[6];
    const float* wq    = (const float*)d_in[7];
    const float* bq    = (const float*)d_in[8];
    const float* wk    = (const float*)d_in[9];
    const float* bk    = (const float*)d_in[10];
    const float* wv    = (const float*)d_in[11];
    const float* bv    = (const float*)d_in[12];
    const float* no_w  = (const float*)d_in[13];
    const float* no_b  = (const float*)d_in[14];
    const float* no_ms = (const float*)d_in[15];
    const float* o_w1  = (const float*)d_in[16];
    const float* o_b1  = (const float*)d_in[17];
    const float* o_w2  = (const float*)d_in[18];
    const float* o_b2  = (const float*)d_in[19];
    const float* pn_w  = (const float*)d_in[20];
    const float* pn_b  = (const float*)d_in[21];
    const float* pn_ms = (const float*)d_in[22];
    const float* p_w1  = (const float*)d_in[23];
    const float* p_b1  = (const float*)d_in[24];
    const float* p_w2  = (const float*)d_in[25];
    const float* p_b2  = (const float*)d_in[26];
    float* out = (float*)d_out;

    const int smem_fin = (3 * 64 * WP + 4 * G * DH + 8 * DH + 2 * G) * 4;
    cudaFuncSetAttribute(k_fused, cudaFuncAttributeMaxDynamicSharedMemorySize, SMEM_FUSED);
    cudaFuncSetAttribute(k_final, cudaFuncAttributeMaxDynamicSharedMemorySize, smem_fin);

    k_xstats<<<96, 256>>>(x);
    k_xnorm<<<60, 256>>>(x, nq_w, nq_b, nq_ms, wq, wk, wv);
    k_fused<<<512, 256, SMEM_FUSED>>>(bq, bk, bv);
    k_hstats<<<12, 256>>>();
    k_final<<<256, 256, smem_fin>>>(x, no_w, no_b, no_ms,
                                    o_w1, o_b1, o_w2, o_b2,
                                    pn_w, pn_b, pn_ms,
                                    p_w1, p_b1, p_w2, p_b2, out);
}

// round 10
// speedup vs baseline: 1.2282x; 1.2282x over previous
#include <cuda_runtime.h>
#include <cuda_bf16.h>
#include <math.h>
#include <string.h>

#define NN   6144
#define G    24
#define DIN  128
#define DH   64
#define NH   8
#define QKV_W 1536

typedef unsigned long long u64;
typedef unsigned int u32;

// ---------------- device scratch --------------------------------------------
__device__ float g_qkv[NN * QKV_W];            // 37.7 MB fp32 qkv
__device__ float g_h[NN * DH];                 // residual-init + attn accum
__device__ unsigned short g_xhi[NN * DIN];
__device__ unsigned short g_xlo[NN * DIN];
__device__ unsigned short g_whi[QKV_W * DIN];
__device__ unsigned short g_wlo[QKV_W * DIN];
__device__ float g_xs_part[96 * DIN];
__device__ float g_xq_part[96 * DIN];
__device__ float g_hsum[DH];
__device__ float g_hsumsq[DH];

// ---------------- PTX helpers -----------------------------------------------
__device__ __forceinline__ u32 smem_u32(const void* p) {
    u32 a;
    asm("{ .reg .u64 t; cvta.to.shared.u64 t, %1; cvt.u32.u64 %0, t; }"
        : "=r"(a) : "l"(p));
    return a;
}
__device__ __forceinline__ void ldsm_x4(u32& r0, u32& r1, u32& r2, u32& r3, u32 addr) {
    asm volatile("ldmatrix.sync.aligned.m8n8.x4.shared.b16 {%0,%1,%2,%3}, [%4];"
                 : "=r"(r0), "=r"(r1), "=r"(r2), "=r"(r3) : "r"(addr));
}
__device__ __forceinline__ void ldsm_x2(u32& r0, u32& r1, u32 addr) {
    asm volatile("ldmatrix.sync.aligned.m8n8.x2.shared.b16 {%0,%1}, [%2];"
                 : "=r"(r0), "=r"(r1) : "r"(addr));
}
__device__ __forceinline__ void mma_bf16(float* d, const u32* a, const u32* b) {
    asm volatile(
        "mma.sync.aligned.m16n8k16.row.col.f32.bf16.bf16.f32 "
        "{%0,%1,%2,%3},{%4,%5,%6,%7},{%8,%9},{%0,%1,%2,%3};"
        : "+f"(d[0]), "+f"(d[1]), "+f"(d[2]), "+f"(d[3])
        : "r"(a[0]), "r"(a[1]), "r"(a[2]), "r"(a[3]), "r"(b[0]), "r"(b[1]));
}

__device__ __forceinline__ unsigned short bf16bits(float v) {
    __nv_bfloat16 b = __float2bfloat16(v);
    unsigned short s; memcpy(&s, &b, 2); return s;
}
__device__ __forceinline__ float bf16val(float v) {
    return __bfloat162float(__float2bfloat16(v));
}

// ---------------- K1: x stats partials --------------------------------------
__global__ void __launch_bounds__(256)
k_xstats(const float* __restrict__ x) {
    __shared__ float smS[8 * 128], smQ[8 * 128];
    int t  = threadIdx.x;
    int c4 = t & 31;
    int rs = t >> 5;
    int r0 = blockIdx.x * 64;

    const float4* xg = (const float4*)x;
    float4 s = make_float4(0.f, 0.f, 0.f, 0.f);
    float4 q = make_float4(0.f, 0.f, 0.f, 0.f);
    #pragma unroll
    for (int r = rs; r < 64; r += 8) {
        float4 v = xg[(size_t)(r0 + r) * 32 + c4];
        s.x += v.x; s.y += v.y; s.z += v.z; s.w += v.w;
        q.x += v.x * v.x; q.y += v.y * v.y; q.z += v.z * v.z; q.w += v.w * v.w;
    }
    ((float4*)smS)[rs * 32 + c4] = s;
    ((float4*)smQ)[rs * 32 + c4] = q;
    __syncthreads();
    if (t < 128) {
        float ss = 0.f, qq = 0.f;
        #pragma unroll
        for (int j = 0; j < 8; j++) { ss += smS[j * 128 + t]; qq += smQ[j * 128 + t]; }
        g_xs_part[blockIdx.x * 128 + t] = ss;
        g_xq_part[blockIdx.x * 128 + t] = qq;
    }
}

// ---------------- K2: normalize x -> bf16 hi/lo; W -> bf16 hi/lo; h init ----
__global__ void __launch_bounds__(256)
k_xnorm(const float* __restrict__ x,
        const float* __restrict__ nq_w, const float* __restrict__ nq_b,
        const float* __restrict__ nq_ms,
        const float* __restrict__ wq, const float* __restrict__ wk,
        const float* __restrict__ wv) {
    int tid = threadIdx.x;
    int b   = blockIdx.x;

    if (b == 0 && tid < DH) { g_hsum[tid] = 0.f; g_hsumsq[tid] = 0.f; }

    uint2* xh = (uint2*)g_xhi;
    uint2* xl = (uint2*)g_xlo;
    uint2* wh = (uint2*)g_whi;
    uint2* wl = (uint2*)g_wlo;

    if (b < 48) {
        __shared__ float As[128], Bs[128];
        if (tid < 128) {
            float ss = 0.f, qq = 0.f;
            #pragma unroll 8
            for (int p = 0; p < 96; p++) {
                ss += g_xs_part[p * 128 + tid];
                qq += g_xq_part[p * 128 + tid];
            }
            const float invN = 1.0f / NN;
            float mean = ss * invN;
            float ex2  = qq * invN;
            float mm   = mean * nq_ms[tid];
            float var  = ex2 - 2.f * mm * mean + mm * mm;
            float rinv = rsqrtf(var + 1e-5f);
            As[tid] = nq_w[tid] * rinv;
            Bs[tid] = nq_b[tid] - nq_w[tid] * rinv * mm;
        }
        __syncthreads();
        int r0 = b * 128;
        const float4* xg = (const float4*)x;
        for (int i = tid; i < 128 * 32; i += 256) {
            int row = i >> 5, c4 = i & 31, c = c4 * 4;
            float4 v = xg[(size_t)(r0 + row) * 32 + c4];
            float f[4];
            f[0] = fmaf(v.x, As[c],     Bs[c]);
            f[1] = fmaf(v.y, As[c + 1], Bs[c + 1]);
            f[2] = fmaf(v.z, As[c + 2], Bs[c + 2]);
            f[3] = fmaf(v.w, As[c + 3], Bs[c + 3]);
            unsigned short h[4], l[4];
            #pragma unroll
            for (int j = 0; j < 4; j++) {
                h[j] = bf16bits(f[j]);
                l[j] = bf16bits(f[j] - bf16val(f[j]));
            }
            uint2 uh, ul;
            uh.x = (u32)h[0] | ((u32)h[1] << 16); uh.y = (u32)h[2] | ((u32)h[3] << 16);
            ul.x = (u32)l[0] | ((u32)l[1] << 16); ul.y = (u32)l[2] | ((u32)l[3] << 16);
            size_t idx = (size_t)(r0 + row) * 32 + c4;
            xh[idx] = uh; xl[idx] = ul;
        }
        // residual init: g_h = x[:, :64] + x[:, 64:]
        float4* h4 = (float4*)g_h;
        for (int i = tid; i < 128 * 16; i += 256) {
            int row = i >> 4, c4 = i & 15;
            float4 xa = xg[(size_t)(r0 + row) * 32 + c4];
            float4 xb = xg[(size_t)(r0 + row) * 32 + 16 + c4];
            h4[(size_t)(r0 + row) * 16 + c4] =
                make_float4(xa.x + xb.x, xa.y + xb.y, xa.z + xb.z, xa.w + xb.w);
        }
    } else {
        int wr0 = (b - 48) * 128;
        for (int i = tid; i < 128 * 32; i += 256) {
            int row = i >> 5, c4 = i & 31;
            int gidx = wr0 + row;
            int mat = gidx >> 9, lr = gidx & 511;
            const float4* src = (const float4*)(mat == 0 ? wq : (mat == 1 ? wk : wv));
            float4 v = src[(size_t)lr * 32 + c4];
            float f[4] = {v.x, v.y, v.z, v.w};
            unsigned short h[4], l[4];
            #pragma unroll
            for (int j = 0; j < 4; j++) {
                h[j] = bf16bits(f[j]);
                l[j] = bf16bits(f[j] - bf16val(f[j]));
            }
            uint2 uh, ul;
            uh.x = (u32)h[0] | ((u32)h[1] << 16); uh.y = (u32)h[2] | ((u32)h[3] << 16);
            ul.x = (u32)l[0] | ((u32)l[1] << 16); ul.y = (u32)l[2] | ((u32)l[3] << 16);
            size_t idx = (size_t)gidx * 32 + c4;
            wh[idx] = uh; wl[idx] = ul;
        }
    }
}

// ---------------- K3: QKV GEMM via mma.sync bf16 split (hi+lo) --------------
#define ROWB 272
#define ATILE (128 * ROWB)
#define BTILE (64 * ROWB)
__global__ void __launch_bounds__(256, 2)
k_qkv(const float* __restrict__ bq, const float* __restrict__ bk,
      const float* __restrict__ bv) {
    extern __shared__ char smc[];
    float* bias_s = (float*)smc;
    char* aH = smc + 512;
    char* aL = aH + ATILE;
    char* bH = aL + ATILE;
    char* bL = bH + BTILE;

    int tid = threadIdx.x;
    int m0 = blockIdx.x * 128;
    int oc = blockIdx.y * 64;
    int mat = oc >> 9, o0 = oc & 511;
    const float* bias = mat == 0 ? bq : (mat == 1 ? bk : bv);
    if (tid < 64) bias_s[tid] = bias[o0 + tid];

    const uint2* xh = (const uint2*)g_xhi;
    const uint2* xl = (const uint2*)g_xlo;
    const uint2* wh = (const uint2*)g_whi;
    const uint2* wl = (const uint2*)g_wlo;

    #pragma unroll
    for (int i = tid; i < 4096; i += 256) {
        int row = i >> 5, c4 = i & 31;
        int so = row * ROWB + c4 * 8;
        size_t ax = (size_t)(m0 + row) * 32 + c4;
        *(uint2*)(aH + so) = xh[ax];
        *(uint2*)(aL + so) = xl[ax];
    }
    #pragma unroll
    for (int i = tid; i < 2048; i += 256) {
        int row = i >> 5, c4 = i & 31;
        int so = row * ROWB + c4 * 8;
        size_t bx = (size_t)(oc + row) * 32 + c4;
        *(uint2*)(bH + so) = wh[bx];
        *(uint2*)(bL + so) = wl[bx];
    }
    __syncthreads();

    u32 sb = smem_u32(smc);
    u32 aHb = sb + 512, aLb = aHb + ATILE, bHb = aLb + ATILE, bLb = bHb + BTILE;

    int t   = tid & 31;
    int wid = tid >> 5;
    int wm = (wid & 3) * 32;
    int wn = (wid >> 2) * 32;
    int rowA = ((t >> 3) & 1) * 8 + (t & 7);
    int kofA = (t >> 4) * 8;
    int rowB = (t & 7);
    int kofB = ((t >> 3) & 1) * 8;

    float acc[2][4][4];
    #pragma unroll
    for (int mf = 0; mf < 2; mf++)
        #pragma unroll
        for (int nf = 0; nf < 4; nf++)
            #pragma unroll
            for (int j = 0; j < 4; j++) acc[mf][nf][j] = 0.f;

    for (int k = 0; k < 128; k += 16) {
        u32 ah[2][4], al[2][4], bh[4][2], bl[4][2];
        #pragma unroll
        for (int mf = 0; mf < 2; mf++) {
            u32 off = (u32)((wm + mf * 16 + rowA) * ROWB + (k + kofA) * 2);
            ldsm_x4(ah[mf][0], ah[mf][1], ah[mf][2], ah[mf][3], aHb + off);
            ldsm_x4(al[mf][0], al[mf][1], al[mf][2], al[mf][3], aLb + off);
        }
        #pragma unroll
        for (int nf = 0; nf < 4; nf++) {
            u32 off = (u32)((wn + nf * 8 + rowB) * ROWB + (k + kofB) * 2);
            ldsm_x2(bh[nf][0], bh[nf][1], bHb + off);
            ldsm_x2(bl[nf][0], bl[nf][1], bLb + off);
        }
        #pragma unroll
        for (int mf = 0; mf < 2; mf++)
            #pragma unroll
            for (int nf = 0; nf < 4; nf++) {
                mma_bf16(acc[mf][nf], ah[mf], bh[nf]);
                mma_bf16(acc[mf][nf], ah[mf], bl[nf]);
                mma_bf16(acc[mf][nf], al[mf], bh[nf]);
            }
    }

    int tq = t >> 2, tr = t & 3;
    #pragma unroll
    for (int mf = 0; mf < 2; mf++) {
        int m = m0 + wm + mf * 16 + tq;
        #pragma unroll
        for (int nf = 0; nf < 4; nf++) {
            int ln = wn + nf * 8 + tr * 2;
            float b0 = bias_s[ln], b1 = bias_s[ln + 1];
            float2 v0 = make_float2(acc[mf][nf][0] + b0, acc[mf][nf][1] + b1);
            float2 v1 = make_float2(acc[mf][nf][2] + b0, acc[mf][nf][3] + b1);
            *(float2*)(g_qkv + (size_t)m * QKV_W + oc + ln) = v0;
            *(float2*)(g_qkv + (size_t)(m + 8) * QKV_W + oc + ln) = v1;
        }
    }
}

// ---------------- K4: per-(set,head) attention -> atomicAdd into g_h --------
__global__ void __launch_bounds__(192, 8)
k_attn() {
    __shared__ float4 q4h[24 * 17];
    __shared__ float4 kt4[16 * 25];
    __shared__ float4 v4h[24 * 16];
    __shared__ float  alpha[24 * 24];

    int tid = threadIdx.x;
    int set = blockIdx.x >> 3;
    int h   = blockIdx.x & 7;
    int n0  = set * G;

    const float4* src4 = (const float4*)g_qkv + (size_t)n0 * 384;
    #pragma unroll
    for (int i = tid; i < 24 * 16; i += 192) {
        int n = i >> 4, c4 = i & 15;
        q4h[n * 17 + c4] = src4[n * 384 + h * 16 + c4];
        v4h[n * 16 + c4] = src4[n * 384 + 256 + h * 16 + c4];
        kt4[c4 * 25 + n] = src4[n * 384 + 128 + h * 16 + c4];
    }
    __syncthreads();

    // logits: 96 threads, each 2 d x 3 s
    if (tid < 96) {
        int d0 = (tid >> 3) * 2;
        int sg = tid & 7;
        float a00 = 0.f, a01 = 0.f, a02 = 0.f;
        float a10 = 0.f, a11 = 0.f, a12 = 0.f;
        #pragma unroll
        for (int j = 0; j < 16; j++) {
            float4 q0 = q4h[d0 * 17 + j];
            float4 q1 = q4h[(d0 + 1) * 17 + j];
            const float4* kp = &kt4[j * 25 + sg * 3];
            float4 k0 = kp[0], k1 = kp[1], k2 = kp[2];
            a00 += q0.x * k0.x + q0.y * k0.y + q0.z * k0.z + q0.w * k0.w;
            a01 += q0.x * k1.x + q0.y * k1.y + q0.z * k1.z + q0.w * k1.w;
            a02 += q0.x * k2.x + q0.y * k2.y + q0.z * k2.z + q0.w * k2.w;
            a10 += q1.x * k0.x + q1.y * k0.y + q1.z * k0.z + q1.w * k0.w;
            a11 += q1.x * k1.x + q1.y * k1.y + q1.z * k1.z + q1.w * k1.w;
            a12 += q1.x * k2.x + q1.y * k2.y + q1.z * k2.z + q1.w * k2.w;
        }
        float* r0 = alpha + d0 * G + sg * 3;
        float* r1 = r0 + G;
        r0[0] = a00 * 0.125f; r0[1] = a01 * 0.125f; r0[2] = a02 * 0.125f;
        r1[0] = a10 * 0.125f; r1[1] = a11 * 0.125f; r1[2] = a12 * 0.125f;
    }
    __syncthreads();

    // softmax per destination d, in-place in smem
    if (tid < G) {
        float* row = alpha + tid * G;
        float m = row[0];
        #pragma unroll
        for (int s = 1; s < G; s++) m = fmaxf(m, row[s]);
        float sum = 0.f;
        #pragma unroll
        for (int s = 0; s < G; s++) {
            float e = expf(row[s] - m);
            row[s] = e;
            sum += e;
        }
        float inv = 1.0f / (sum + 1e-16f);
        #pragma unroll
        for (int s = 0; s < G; s++) row[s] *= inv;
    }
    __syncthreads();

    // aggregate: thread = (dg, c4), 4 destinations share each V read
    if (tid < 96) {
        int dg = tid >> 4;           // 0..5
        int c4 = tid & 15;           // 0..15
        int d0 = dg * 4;
        float4 acc[4];
        #pragma unroll
        for (int i = 0; i < 4; i++) acc[i] = make_float4(0.f, 0.f, 0.f, 0.f);
        #pragma unroll
        for (int s = 0; s < G; s++) {
            float4 vv = v4h[s * 16 + c4];
            #pragma unroll
            for (int i = 0; i < 4; i++) {
                float a = alpha[(d0 + i) * G + s];
                acc[i].x = fmaf(a, vv.x, acc[i].x);
                acc[i].y = fmaf(a, vv.y, acc[i].y);
                acc[i].z = fmaf(a, vv.z, acc[i].z);
                acc[i].w = fmaf(a, vv.w, acc[i].w);
            }
        }
        #pragma unroll
        for (int i = 0; i < 4; i++) {
            float* dst = g_h + (size_t)(n0 + d0 + i) * DH + c4 * 4;
            atomicAdd(dst + 0, acc[i].x * 0.125f);
            atomicAdd(dst + 1, acc[i].y * 0.125f);
            atomicAdd(dst + 2, acc[i].z * 0.125f);
            atomicAdd(dst + 3, acc[i].w * 0.125f);
        }
    }
}

// ---------------- K5: h stats (96 blocks x 64 rows) -------------------------
__global__ void __launch_bounds__(256)
k_hstats() {
    __shared__ float smS[16 * 64], smQ[16 * 64];
    int t  = threadIdx.x;
    int c4 = t & 15;
    int rs = t >> 4;
    int r0 = blockIdx.x * 64;

    const float4* h4 = (const float4*)g_h;
    float4 s = make_float4(0.f, 0.f, 0.f, 0.f);
    float4 q = make_float4(0.f, 0.f, 0.f, 0.f);
    #pragma unroll
    for (int r = rs; r < 64; r += 16) {
        float4 a = h4[(size_t)(r0 + r) * 16 + c4];
        s.x += a.x; s.y += a.y; s.z += a.z; s.w += a.w;
        q.x += a.x * a.x; q.y += a.y * a.y; q.z += a.z * a.z; q.w += a.w * a.w;
    }
    ((float4*)smS)[rs * 16 + c4] = s;
    ((float4*)smQ)[rs * 16 + c4] = q;
    __syncthreads();
    if (t < 64) {
        float ss = 0.f, qq = 0.f;
        #pragma unroll
        for (int j = 0; j < 16; j++) { ss += smS[j * 64 + t]; qq += smQ[j * 64 + t]; }
        atomicAdd(&g_hsum[t], ss);
        atomicAdd(&g_hsumsq[t], qq);
    }
}

__device__ __forceinline__ float gelu_exact(float v) {
    return 0.5f * v * (1.0f + erff(v * 0.70710678118654752f));
}

// ---------------- K6: global norm + PFF + per-set norm + score + pooling ----
#define WP 65
__global__ void __launch_bounds__(256)
k_final(const float* __restrict__ x,
        const float* __restrict__ no_w, const float* __restrict__ no_b,
        const float* __restrict__ no_ms,
        const float* __restrict__ o_w1, const float* __restrict__ o_b1,
        const float* __restrict__ o_w2, const float* __restrict__ o_b2,
        const float* __restrict__ pn_w, const float* __restrict__ pn_b,
        const float* __restrict__ pn_ms,
        const float* __restrict__ p_w1, const float* __restrict__ p_b1,
        const float* __restrict__ p_w2, const float* __restrict__ p_b2,
        float* __restrict__ out) {
    extern __shared__ float dsm[];
    float* w1T  = dsm;
    float* w2T  = w1T + 64 * WP;
    float* pw1T = w2T + 64 * WP;
    float* hs   = pw1T + 64 * WP;
    float* hn   = hs + G * DH;
    float* t1   = hn + G * DH;
    float* h2   = t1 + G * DH;
    float* a2   = h2 + G * DH;
    float* b2   = a2 + DH;
    float* cm   = b2 + DH;
    float* cr   = cm + DH;
    float* b1s  = cr + DH;
    float* b2s  = b1s + DH;
    float* pb1s = b2s + DH;
    float* pw2s = pb1s + DH;
    float* score = pw2s + DH;
    float* wsf   = score + G;

    int tid = threadIdx.x;
    int n0  = blockIdx.x * G;

    for (int i = tid; i < 64 * 64; i += 256) {
        int j = i >> 6, c = i & 63;
        w1T[c * WP + j]  = o_w1[i];
        w2T[c * WP + j]  = o_w2[i];
        pw1T[c * WP + j] = p_w1[i];
    }
    if (tid < DH) {
        b1s[tid] = o_b1[tid]; b2s[tid] = o_b2[tid];
        pb1s[tid] = p_b1[tid]; pw2s[tid] = p_w2[tid];
        const float invN = 1.0f / NN;
        float mean = g_hsum[tid] * invN;
        float ex2  = g_hsumsq[tid] * invN;
        float mm   = mean * no_ms[tid];
        float var  = ex2 - 2.f * mm * mean + mm * mm;
        float rinv = rsqrtf(var + 1e-5f);
        a2[tid] = no_w[tid] * rinv;
        b2[tid] = no_b[tid] - no_w[tid] * rinv * mm;
    }
    for (int i = tid; i < G * DH; i += 256) hs[i] = g_h[(size_t)n0 * DH + i];
    __syncthreads();

    for (int i = tid; i < G * DH; i += 256) {
        int c = i & 63;
        hn[i] = fmaf(hs[i], a2[c], b2[c]);
    }
    __syncthreads();

    // t1 = gelu(hn @ o_w1^T + b1), 2d x 2j blocking (384 quad-items)
    for (int i = tid; i < 384; i += 256) {
        int dp = i >> 5, jp = i & 31;
        int d0 = dp * 2;
        float a00 = b1s[jp],      a01 = b1s[jp + 32];
        float a10 = a00,          a11 = a01;
        const float* h0 = hn + d0 * DH;
        const float* h1 = h0 + DH;
        #pragma unroll 16
        for (int c = 0; c < DH; c++) {
            float w0 = w1T[c * WP + jp], w1 = w1T[c * WP + jp + 32];
            float hc0 = h0[c], hc1 = h1[c];
            a00 = fmaf(hc0, w0, a00); a01 = fmaf(hc0, w1, a01);
            a10 = fmaf(hc1, w0, a10); a11 = fmaf(hc1, w1, a11);
        }
        t1[d0 * DH + jp]            = gelu_exact(a00);
        t1[d0 * DH + jp + 32]       = gelu_exact(a01);
        t1[(d0 + 1) * DH + jp]      = gelu_exact(a10);
        t1[(d0 + 1) * DH + jp + 32] = gelu_exact(a11);
    }
    __syncthreads();

    // h2 = hs + t1 @ o_w2^T + b2, 2d x 2c blocking
    for (int i = tid; i < 384; i += 256) {
        int dp = i >> 5, cp = i & 31;
        int d0 = dp * 2;
        float a00 = b2s[cp],      a01 = b2s[cp + 32];
        float a10 = a00,          a11 = a01;
        const float* t0 = t1 + d0 * DH;
        const float* t1r = t0 + DH;
        #pragma unroll 16
        for (int j = 0; j < DH; j++) {
            float w0 = w2T[j * WP + cp], w1 = w2T[j * WP + cp + 32];
            float tc0 = t0[j], tc1 = t1r[j];
            a00 = fmaf(tc0, w0, a00); a01 = fmaf(tc0, w1, a01);
            a10 = fmaf(tc1, w0, a10); a11 = fmaf(tc1, w1, a11);
        }
        h2[d0 * DH + cp]            = hs[d0 * DH + cp] + a00;
        h2[d0 * DH + cp + 32]       = hs[d0 * DH + cp + 32] + a01;
        h2[(d0 + 1) * DH + cp]      = hs[(d0 + 1) * DH + cp] + a10;
        h2[(d0 + 1) * DH + cp + 32] = hs[(d0 + 1) * DH + cp + 32] + a11;
    }
    __syncthreads();

    if (tid < DH) {
        int c = tid;
        float m = 0.f;
        #pragma unroll
        for (int d = 0; d < G; d++) m += h2[d * DH + c];
        m *= (1.0f / G);
        float mm = m * pn_ms[c];
        float vv = 0.f;
        #pragma unroll
        for (int d = 0; d < G; d++) { float t = h2[d * DH + c] - mm; vv += t * t; }
        vv *= (1.0f / G);
        cm[c] = mm;
        cr[c] = pn_w[c] * rsqrtf(vv + 1e-5f);
    }
    __syncthreads();

    for (int i = tid; i < G * DH; i += 256) {
        int c = i & 63;
        hn[i] = fmaf(h2[i] - cm[c], cr[c], pn_b[c]);
    }
    __syncthreads();

    // t2 = gelu(hn @ p_w1^T + pb1), 2d x 2j blocking
    for (int i = tid; i < 384; i += 256) {
        int dp = i >> 5, jp = i & 31;
        int d0 = dp * 2;
        float a00 = pb1s[jp],     a01 = pb1s[jp + 32];
        float a10 = a00,          a11 = a01;
        const float* h0 = hn + d0 * DH;
        const float* h1 = h0 + DH;
        #pragma unroll 16
        for (int c = 0; c < DH; c++) {
            float w0 = pw1T[c * WP + jp], w1 = pw1T[c * WP + jp + 32];
            float hc0 = h0[c], hc1 = h1[c];
            a00 = fmaf(hc0, w0, a00); a01 = fmaf(hc0, w1, a01);
            a10 = fmaf(hc1, w0, a10); a11 = fmaf(hc1, w1, a11);
        }
        t1[d0 * DH + jp]            = gelu_exact(a00);
        t1[d0 * DH + jp + 32]       = gelu_exact(a01);
        t1[(d0 + 1) * DH + jp]      = gelu_exact(a10);
        t1[(d0 + 1) * DH + jp + 32] = gelu_exact(a11);
    }
    __syncthreads();

    if (tid < G) {
        float acc = p_b2[0];
        const float* tr = t1 + tid * DH;
        #pragma unroll 16
        for (int j = 0; j < DH; j++) acc = fmaf(tr[j], pw2s[j], acc);
        score[tid] = acc;
    }
    __syncthreads();

    if (tid == 0) {
        float m = score[0];
        #pragma unroll
        for (int d = 1; d < G; d++) m = fmaxf(m, score[d]);
        float sum = 0.f;
        #pragma unroll
        for (int d = 0; d < G; d++) { wsf[d] = expf(score[d] - m); sum += wsf[d]; }
        float inv = 1.0f / (sum + 1e-16f);
        #pragma unroll
        for (int d = 0; d < G; d++) wsf[d] *= inv;
    }
    __syncthreads();

    if (tid < DIN) {
        float acc = 0.f;
        #pragma unroll
        for (int d = 0; d < G; d++)
            acc = fmaf(wsf[d], x[(size_t)(n0 + d) * DIN + tid], acc);
        out[blockIdx.x * DIN + tid] = acc;
    }
}

// ---------------- launch -----------------------------------------------------
extern "C" void kernel_launch(void* const* d_in, const int* in_sizes, int n_in,
                              void* d_out, int out_size) {
    const float* x     = (const float*)d_in[0];
    const float* nq_w  = (const float*)d_in[4];
    const float* nq_b  = (const float*)d_in[5];
    const float* nq_ms = (const float*)d_in[6];
    const float* wq    = (const float*)d_in[7];
    const float* bq    = (const float*)d_in[8];
    const float* wk    = (const float*)d_in[9];
    const float* bk    = (const float*)d_in[10];
    const float* wv    = (const float*)d_in[11];
    const float* bv    = (const float*)d_in[12];
    const float* no_w  = (const float*)d_in[13];
    const float* no_b  = (const float*)d_in[14];
    const float* no_ms = (const float*)d_in[15];
    const float* o_w1  = (const float*)d_in[16];
    const float* o_b1  = (const float*)d_in[17];
    const float* o_w2  = (const float*)d_in[18];
    const float* o_b2  = (const float*)d_in[19];
    const float* pn_w  = (const float*)d_in[20];
    const float* pn_b  = (const float*)d_in[21];
    const float* pn_ms = (const float*)d_in[22];
    const float* p_w1  = (const float*)d_in[23];
    const float* p_b1  = (const float*)d_in[24];
    const float* p_w2  = (const float*)d_in[25];
    const float* p_b2  = (const float*)d_in[26];
    float* out = (float*)d_out;

    const int smem_qkv = 512 + 2 * ATILE + 2 * BTILE;                        // 104,960 B
    const int smem_fin = (3 * 64 * WP + 4 * G * DH + 8 * DH + 2 * G) * 4;    // ~77 KB
    cudaFuncSetAttribute(k_qkv,   cudaFuncAttributeMaxDynamicSharedMemorySize, smem_qkv);
    cudaFuncSetAttribute(k_final, cudaFuncAttributeMaxDynamicSharedMemorySize, smem_fin);

    k_xstats<<<96, 256>>>(x);
    k_xnorm<<<60, 256>>>(x, nq_w, nq_b, nq_ms, wq, wk, wv);
    k_qkv<<<dim3(48, 24), 256, smem_qkv>>>(bq, bk, bv);
    k_attn<<<2048, 192>>>();
    k_hstats<<<96, 256>>>();
    k_final<<<256, 256, smem_fin>>>(x, no_w, no_b, no_ms,
                                    o_w1, o_b1, o_w2, o_b2,
                                    pn_w, pn_b, pn_ms,
                                    p_w1, p_b1, p_w2, p_b2, out);
}

// round 11
// speedup vs baseline: 1.2408x; 1.0102x over previous
#include <cuda_runtime.h>
#include <cuda_bf16.h>
#include <math.h>
#include <string.h>

#define NN   6144
#define G    24
#define DIN  128
#define DH   64
#define NH   8
#define QKV_W 1536

typedef unsigned long long u64;
typedef unsigned int u32;

// ---------------- device scratch --------------------------------------------
__device__ float g_qkv[NN * QKV_W];
__device__ float g_h[NN * DH];
__device__ unsigned short g_xhi[NN * DIN];
__device__ unsigned short g_xlo[NN * DIN];
__device__ unsigned short g_whi[QKV_W * DIN];
__device__ unsigned short g_wlo[QKV_W * DIN];
__device__ float g_xs_part[96 * DIN];
__device__ float g_xq_part[96 * DIN];
__device__ float g_hsum[DH];
__device__ float g_hsumsq[DH];

// ---------------- PTX helpers -----------------------------------------------
__device__ __forceinline__ u32 smem_u32(const void* p) {
    u32 a;
    asm("{ .reg .u64 t; cvta.to.shared.u64 t, %1; cvt.u32.u64 %0, t; }"
        : "=r"(a) : "l"(p));
    return a;
}
__device__ __forceinline__ void ldsm_x4(u32& r0, u32& r1, u32& r2, u32& r3, u32 addr) {
    asm volatile("ldmatrix.sync.aligned.m8n8.x4.shared.b16 {%0,%1,%2,%3}, [%4];"
                 : "=r"(r0), "=r"(r1), "=r"(r2), "=r"(r3) : "r"(addr));
}
__device__ __forceinline__ void ldsm_x2(u32& r0, u32& r1, u32 addr) {
    asm volatile("ldmatrix.sync.aligned.m8n8.x2.shared.b16 {%0,%1}, [%2];"
                 : "=r"(r0), "=r"(r1) : "r"(addr));
}
__device__ __forceinline__ void mma_bf16(float* d, const u32* a, const u32* b) {
    asm volatile(
        "mma.sync.aligned.m16n8k16.row.col.f32.bf16.bf16.f32 "
        "{%0,%1,%2,%3},{%4,%5,%6,%7},{%8,%9},{%0,%1,%2,%3};"
        : "+f"(d[0]), "+f"(d[1]), "+f"(d[2]), "+f"(d[3])
        : "r"(a[0]), "r"(a[1]), "r"(a[2]), "r"(a[3]), "r"(b[0]), "r"(b[1]));
}
__device__ __forceinline__ u64 pack2(float lo, float hi) {
    u64 r; asm("mov.b64 %0,{%1,%2};" : "=l"(r) : "f"(lo), "f"(hi)); return r;
}
__device__ __forceinline__ u64 fma2(u64 a, u64 b, u64 c) {
    u64 d; asm("fma.rn.f32x2 %0,%1,%2,%3;" : "=l"(d) : "l"(a), "l"(b), "l"(c)); return d;
}
__device__ __forceinline__ void unpack2(u64 v, float& lo, float& hi) {
    asm("mov.b64 {%0,%1},%2;" : "=f"(lo), "=f"(hi) : "l"(v));
}

__device__ __forceinline__ unsigned short bf16bits(float v) {
    __nv_bfloat16 b = __float2bfloat16(v);
    unsigned short s; memcpy(&s, &b, 2); return s;
}
__device__ __forceinline__ float bf16val(float v) {
    return __bfloat162float(__float2bfloat16(v));
}

// ---------------- K1: x stats partials --------------------------------------
__global__ void __launch_bounds__(256)
k_xstats(const float* __restrict__ x) {
    __shared__ float smS[8 * 128], smQ[8 * 128];
    int t  = threadIdx.x;
    int c4 = t & 31;
    int rs = t >> 5;
    int r0 = blockIdx.x * 64;

    const float4* xg = (const float4*)x;
    float4 s = make_float4(0.f, 0.f, 0.f, 0.f);
    float4 q = make_float4(0.f, 0.f, 0.f, 0.f);
    #pragma unroll
    for (int r = rs; r < 64; r += 8) {
        float4 v = xg[(size_t)(r0 + r) * 32 + c4];
        s.x += v.x; s.y += v.y; s.z += v.z; s.w += v.w;
        q.x += v.x * v.x; q.y += v.y * v.y; q.z += v.z * v.z; q.w += v.w * v.w;
    }
    ((float4*)smS)[rs * 32 + c4] = s;
    ((float4*)smQ)[rs * 32 + c4] = q;
    __syncthreads();
    if (t < 128) {
        float ss = 0.f, qq = 0.f;
        #pragma unroll
        for (int j = 0; j < 8; j++) { ss += smS[j * 128 + t]; qq += smQ[j * 128 + t]; }
        g_xs_part[blockIdx.x * 128 + t] = ss;
        g_xq_part[blockIdx.x * 128 + t] = qq;
    }
}

// ---------------- K2: normalize x -> bf16 hi/lo; W -> bf16 hi/lo; h init ----
__global__ void __launch_bounds__(256)
k_xnorm(const float* __restrict__ x,
        const float* __restrict__ nq_w, const float* __restrict__ nq_b,
        const float* __restrict__ nq_ms,
        const float* __restrict__ wq, const float* __restrict__ wk,
        const float* __restrict__ wv) {
    int tid = threadIdx.x;
    int b   = blockIdx.x;

    if (b == 0 && tid < DH) { g_hsum[tid] = 0.f; g_hsumsq[tid] = 0.f; }

    uint2* xh = (uint2*)g_xhi;
    uint2* xl = (uint2*)g_xlo;
    uint2* wh = (uint2*)g_whi;
    uint2* wl = (uint2*)g_wlo;

    if (b < 48) {
        __shared__ float As[128], Bs[128];
        if (tid < 128) {
            float ss = 0.f, qq = 0.f;
            #pragma unroll 8
            for (int p = 0; p < 96; p++) {
                ss += g_xs_part[p * 128 + tid];
                qq += g_xq_part[p * 128 + tid];
            }
            const float invN = 1.0f / NN;
            float mean = ss * invN;
            float ex2  = qq * invN;
            float mm   = mean * nq_ms[tid];
            float var  = ex2 - 2.f * mm * mean + mm * mm;
            float rinv = rsqrtf(var + 1e-5f);
            As[tid] = nq_w[tid] * rinv;
            Bs[tid] = nq_b[tid] - nq_w[tid] * rinv * mm;
        }
        __syncthreads();
        int r0 = b * 128;
        const float4* xg = (const float4*)x;
        for (int i = tid; i < 128 * 32; i += 256) {
            int row = i >> 5, c4 = i & 31, c = c4 * 4;
            float4 v = xg[(size_t)(r0 + row) * 32 + c4];
            float f[4];
            f[0] = fmaf(v.x, As[c],     Bs[c]);
            f[1] = fmaf(v.y, As[c + 1], Bs[c + 1]);
            f[2] = fmaf(v.z, As[c + 2], Bs[c + 2]);
            f[3] = fmaf(v.w, As[c + 3], Bs[c + 3]);
            unsigned short h[4], l[4];
            #pragma unroll
            for (int j = 0; j < 4; j++) {
                h[j] = bf16bits(f[j]);
                l[j] = bf16bits(f[j] - bf16val(f[j]));
            }
            uint2 uh, ul;
            uh.x = (u32)h[0] | ((u32)h[1] << 16); uh.y = (u32)h[2] | ((u32)h[3] << 16);
            ul.x = (u32)l[0] | ((u32)l[1] << 16); ul.y = (u32)l[2] | ((u32)l[3] << 16);
            size_t idx = (size_t)(r0 + row) * 32 + c4;
            xh[idx] = uh; xl[idx] = ul;
        }
        // residual init: g_h = x[:, :64] + x[:, 64:]
        float4* h4 = (float4*)g_h;
        for (int i = tid; i < 128 * 16; i += 256) {
            int row = i >> 4, c4 = i & 15;
            float4 xa = xg[(size_t)(r0 + row) * 32 + c4];
            float4 xb = xg[(size_t)(r0 + row) * 32 + 16 + c4];
            h4[(size_t)(r0 + row) * 16 + c4] =
                make_float4(xa.x + xb.x, xa.y + xb.y, xa.z + xb.z, xa.w + xb.w);
        }
    } else {
        int wr0 = (b - 48) * 128;
        for (int i = tid; i < 128 * 32; i += 256) {
            int row = i >> 5, c4 = i & 31;
            int gidx = wr0 + row;
            int mat = gidx >> 9, lr = gidx & 511;
            const float4* src = (const float4*)(mat == 0 ? wq : (mat == 1 ? wk : wv));
            float4 v = src[(size_t)lr * 32 + c4];
            float f[4] = {v.x, v.y, v.z, v.w};
            unsigned short h[4], l[4];
            #pragma unroll
            for (int j = 0; j < 4; j++) {
                h[j] = bf16bits(f[j]);
                l[j] = bf16bits(f[j] - bf16val(f[j]));
            }
            uint2 uh, ul;
            uh.x = (u32)h[0] | ((u32)h[1] << 16); uh.y = (u32)h[2] | ((u32)h[3] << 16);
            ul.x = (u32)l[0] | ((u32)l[1] << 16); ul.y = (u32)l[2] | ((u32)l[3] << 16);
            size_t idx = (size_t)gidx * 32 + c4;
            wh[idx] = uh; wl[idx] = ul;
        }
    }
}

// ---------------- K3: QKV GEMM via mma.sync bf16 split (hi+lo) --------------
#define ROWB 272
#define ATILE (128 * ROWB)
#define BTILE (64 * ROWB)
__global__ void __launch_bounds__(256, 2)
k_qkv(const float* __restrict__ bq, const float* __restrict__ bk,
      const float* __restrict__ bv) {
    extern __shared__ char smc[];
    float* bias_s = (float*)smc;
    char* aH = smc + 512;
    char* aL = aH + ATILE;
    char* bH = aL + ATILE;
    char* bL = bH + BTILE;

    int tid = threadIdx.x;
    int m0 = blockIdx.x * 128;
    int oc = blockIdx.y * 64;
    int mat = oc >> 9, o0 = oc & 511;
    const float* bias = mat == 0 ? bq : (mat == 1 ? bk : bv);
    if (tid < 64) bias_s[tid] = bias[o0 + tid];

    const uint2* xh = (const uint2*)g_xhi;
    const uint2* xl = (const uint2*)g_xlo;
    const uint2* wh = (const uint2*)g_whi;
    const uint2* wl = (const uint2*)g_wlo;

    #pragma unroll
    for (int i = tid; i < 4096; i += 256) {
        int row = i >> 5, c4 = i & 31;
        int so = row * ROWB + c4 * 8;
        size_t ax = (size_t)(m0 + row) * 32 + c4;
        *(uint2*)(aH + so) = xh[ax];
        *(uint2*)(aL + so) = xl[ax];
    }
    #pragma unroll
    for (int i = tid; i < 2048; i += 256) {
        int row = i >> 5, c4 = i & 31;
        int so = row * ROWB + c4 * 8;
        size_t bx = (size_t)(oc + row) * 32 + c4;
        *(uint2*)(bH + so) = wh[bx];
        *(uint2*)(bL + so) = wl[bx];
    }
    __syncthreads();

    u32 sb = smem_u32(smc);
    u32 aHb = sb + 512, aLb = aHb + ATILE, bHb = aLb + ATILE, bLb = bHb + BTILE;

    int t   = tid & 31;
    int wid = tid >> 5;
    int wm = (wid & 3) * 32;
    int wn = (wid >> 2) * 32;
    int rowA = ((t >> 3) & 1) * 8 + (t & 7);
    int kofA = (t >> 4) * 8;
    int rowB = (t & 7);
    int kofB = ((t >> 3) & 1) * 8;

    float acc[2][4][4];
    #pragma unroll
    for (int mf = 0; mf < 2; mf++)
        #pragma unroll
        for (int nf = 0; nf < 4; nf++)
            #pragma unroll
            for (int j = 0; j < 4; j++) acc[mf][nf][j] = 0.f;

    for (int k = 0; k < 128; k += 16) {
        u32 ah[2][4], al[2][4], bh[4][2], bl[4][2];
        #pragma unroll
        for (int mf = 0; mf < 2; mf++) {
            u32 off = (u32)((wm + mf * 16 + rowA) * ROWB + (k + kofA) * 2);
            ldsm_x4(ah[mf][0], ah[mf][1], ah[mf][2], ah[mf][3], aHb + off);
            ldsm_x4(al[mf][0], al[mf][1], al[mf][2], al[mf][3], aLb + off);
        }
        #pragma unroll
        for (int nf = 0; nf < 4; nf++) {
            u32 off = (u32)((wn + nf * 8 + rowB) * ROWB + (k + kofB) * 2);
            ldsm_x2(bh[nf][0], bh[nf][1], bHb + off);
            ldsm_x2(bl[nf][0], bl[nf][1], bLb + off);
        }
        #pragma unroll
        for (int mf = 0; mf < 2; mf++)
            #pragma unroll
            for (int nf = 0; nf < 4; nf++) {
                mma_bf16(acc[mf][nf], ah[mf], bh[nf]);
                mma_bf16(acc[mf][nf], ah[mf], bl[nf]);
                mma_bf16(acc[mf][nf], al[mf], bh[nf]);
            }
    }

    int tq = t >> 2, tr = t & 3;
    #pragma unroll
    for (int mf = 0; mf < 2; mf++) {
        int m = m0 + wm + mf * 16 + tq;
        #pragma unroll
        for (int nf = 0; nf < 4; nf++) {
            int ln = wn + nf * 8 + tr * 2;
            float b0 = bias_s[ln], b1 = bias_s[ln + 1];
            float2 v0 = make_float2(acc[mf][nf][0] + b0, acc[mf][nf][1] + b1);
            float2 v1 = make_float2(acc[mf][nf][2] + b0, acc[mf][nf][3] + b1);
            *(float2*)(g_qkv + (size_t)m * QKV_W + oc + ln) = v0;
            *(float2*)(g_qkv + (size_t)(m + 8) * QKV_W + oc + ln) = v1;
        }
    }
}

// ---------------- K4: per-(set,head) attention, f32x2 math ------------------
__global__ void __launch_bounds__(192)
k_attn() {
    __shared__ float4 q4h[24 * 17];
    __shared__ float4 kt4[16 * 25];
    __shared__ float4 v4h[24 * 16];
    __shared__ __align__(16) float alphaT[24 * 24];   // [s][d]

    int tid = threadIdx.x;
    int set = blockIdx.x >> 3;
    int h   = blockIdx.x & 7;
    int n0  = set * G;

    const float4* src4 = (const float4*)g_qkv + (size_t)n0 * 384;
    #pragma unroll
    for (int i = tid; i < 24 * 16; i += 192) {
        int n = i >> 4, c4 = i & 15;
        q4h[n * 17 + c4] = src4[n * 384 + h * 16 + c4];
        v4h[n * 16 + c4] = src4[n * 384 + 256 + h * 16 + c4];
        kt4[c4 * 25 + n] = src4[n * 384 + 128 + h * 16 + c4];
    }
    __syncthreads();

    // logits: 96 threads, each 2 d x 3 s, packed dot products
    const ulonglong2* q8 = (const ulonglong2*)q4h;
    const ulonglong2* k8 = (const ulonglong2*)kt4;
    if (tid < 96) {
        int d0 = (tid >> 3) * 2;
        int sg = tid & 7;
        u64 a00 = 0, a01 = 0, a02 = 0, a10 = 0, a11 = 0, a12 = 0;
        #pragma unroll
        for (int j = 0; j < 16; j++) {
            ulonglong2 q0 = q8[d0 * 17 + j];
            ulonglong2 q1 = q8[(d0 + 1) * 17 + j];
            ulonglong2 k0 = k8[j * 25 + sg * 3];
            ulonglong2 k1 = k8[j * 25 + sg * 3 + 1];
            ulonglong2 k2 = k8[j * 25 + sg * 3 + 2];
            a00 = fma2(q0.x, k0.x, a00); a00 = fma2(q0.y, k0.y, a00);
            a01 = fma2(q0.x, k1.x, a01); a01 = fma2(q0.y, k1.y, a01);
            a02 = fma2(q0.x, k2.x, a02); a02 = fma2(q0.y, k2.y, a02);
            a10 = fma2(q1.x, k0.x, a10); a10 = fma2(q1.y, k0.y, a10);
            a11 = fma2(q1.x, k1.x, a11); a11 = fma2(q1.y, k1.y, a11);
            a12 = fma2(q1.x, k2.x, a12); a12 = fma2(q1.y, k2.y, a12);
        }
        float lo, hi;
        int s0 = sg * 3;
        unpack2(a00, lo, hi); alphaT[(s0 + 0) * 24 + d0]     = (lo + hi) * 0.125f;
        unpack2(a01, lo, hi); alphaT[(s0 + 1) * 24 + d0]     = (lo + hi) * 0.125f;
        unpack2(a02, lo, hi); alphaT[(s0 + 2) * 24 + d0]     = (lo + hi) * 0.125f;
        unpack2(a10, lo, hi); alphaT[(s0 + 0) * 24 + d0 + 1] = (lo + hi) * 0.125f;
        unpack2(a11, lo, hi); alphaT[(s0 + 1) * 24 + d0 + 1] = (lo + hi) * 0.125f;
        unpack2(a12, lo, hi); alphaT[(s0 + 2) * 24 + d0 + 1] = (lo + hi) * 0.125f;
    }
    __syncthreads();

    // softmax per destination d (column of alphaT)
    if (tid < G) {
        int d = tid;
        float m = alphaT[d];
        #pragma unroll
        for (int s = 1; s < G; s++) m = fmaxf(m, alphaT[s * 24 + d]);
        float sum = 0.f;
        #pragma unroll
        for (int s = 0; s < G; s++) {
            float e = expf(alphaT[s * 24 + d] - m);
            alphaT[s * 24 + d] = e;
            sum += e;
        }
        float inv = 1.0f / (sum + 1e-16f);
        #pragma unroll
        for (int s = 0; s < G; s++) alphaT[s * 24 + d] *= inv;
    }
    __syncthreads();

    // aggregate: thread = (dg, c4), 4 dests; packed channel pairs
    if (tid < 96) {
        int dg = tid >> 4, c4 = tid & 15, d0 = dg * 4;
        const ulonglong2* v8 = (const ulonglong2*)v4h;
        u64 acc[4][2];
        #pragma unroll
        for (int i2 = 0; i2 < 4; i2++) { acc[i2][0] = 0ull; acc[i2][1] = 0ull; }
        #pragma unroll
        for (int s = 0; s < G; s++) {
            float4 al = *(const float4*)&alphaT[s * 24 + d0];
            ulonglong2 vv = v8[s * 16 + c4];
            u64 p;
            p = pack2(al.x, al.x); acc[0][0] = fma2(p, vv.x, acc[0][0]); acc[0][1] = fma2(p, vv.y, acc[0][1]);
            p = pack2(al.y, al.y); acc[1][0] = fma2(p, vv.x, acc[1][0]); acc[1][1] = fma2(p, vv.y, acc[1][1]);
            p = pack2(al.z, al.z); acc[2][0] = fma2(p, vv.x, acc[2][0]); acc[2][1] = fma2(p, vv.y, acc[2][1]);
            p = pack2(al.w, al.w); acc[3][0] = fma2(p, vv.x, acc[3][0]); acc[3][1] = fma2(p, vv.y, acc[3][1]);
        }
        #pragma unroll
        for (int i2 = 0; i2 < 4; i2++) {
            float* dst = g_h + (size_t)(n0 + d0 + i2) * DH + c4 * 4;
            float x0, x1, x2, x3;
            unpack2(acc[i2][0], x0, x1);
            unpack2(acc[i2][1], x2, x3);
            atomicAdd(dst + 0, x0 * 0.125f);
            atomicAdd(dst + 1, x1 * 0.125f);
            atomicAdd(dst + 2, x2 * 0.125f);
            atomicAdd(dst + 3, x3 * 0.125f);
        }
    }
}

// ---------------- K5: h stats (96 blocks x 64 rows) -------------------------
__global__ void __launch_bounds__(256)
k_hstats() {
    __shared__ float smS[16 * 64], smQ[16 * 64];
    int t  = threadIdx.x;
    int c4 = t & 15;
    int rs = t >> 4;
    int r0 = blockIdx.x * 64;

    const float4* h4 = (const float4*)g_h;
    float4 s = make_float4(0.f, 0.f, 0.f, 0.f);
    float4 q = make_float4(0.f, 0.f, 0.f, 0.f);
    #pragma unroll
    for (int r = rs; r < 64; r += 16) {
        float4 a = h4[(size_t)(r0 + r) * 16 + c4];
        s.x += a.x; s.y += a.y; s.z += a.z; s.w += a.w;
        q.x += a.x * a.x; q.y += a.y * a.y; q.z += a.z * a.z; q.w += a.w * a.w;
    }
    ((float4*)smS)[rs * 16 + c4] = s;
    ((float4*)smQ)[rs * 16 + c4] = q;
    __syncthreads();
    if (t < 64) {
        float ss = 0.f, qq = 0.f;
        #pragma unroll
        for (int j = 0; j < 16; j++) { ss += smS[j * 64 + t]; qq += smQ[j * 64 + t]; }
        atomicAdd(&g_hsum[t], ss);
        atomicAdd(&g_hsumsq[t], qq);
    }
}

__device__ __forceinline__ float gelu_exact(float v) {
    return 0.5f * v * (1.0f + erff(v * 0.70710678118654752f));
}

// ---------------- K6: global norm + PFF + per-set norm + score + pooling ----
// weights staged PACKED as u64 pairs along the accumulation dim
#define WPU 65   // u64 pitch
__global__ void __launch_bounds__(256)
k_final(const float* __restrict__ x,
        const float* __restrict__ no_w, const float* __restrict__ no_b,
        const float* __restrict__ no_ms,
        const float* __restrict__ o_w1, const float* __restrict__ o_b1,
        const float* __restrict__ o_w2, const float* __restrict__ o_b2,
        const float* __restrict__ pn_w, const float* __restrict__ pn_b,
        const float* __restrict__ pn_ms,
        const float* __restrict__ p_w1, const float* __restrict__ p_b1,
        const float* __restrict__ p_w2, const float* __restrict__ p_b2,
        float* __restrict__ out) {
    extern __shared__ float dsm[];
    u64*  w1P  = (u64*)dsm;              // [32 c2][65] packed over input-c
    u64*  w2P  = w1P + 32 * WPU;         // [32 j2][65] packed over inner-j
    u64*  pw1P = w2P + 32 * WPU;         // [32 c2][65]
    u64*  pw2P = pw1P + 32 * WPU;        // [32] packed p_w2
    float* hs  = (float*)(pw2P + 32);
    float* hn  = hs + G * DH;
    float* t1  = hn + G * DH;
    float* h2  = t1 + G * DH;
    float* a2  = h2 + G * DH;
    float* b2v = a2 + DH;
    float* cm  = b2v + DH;
    float* cr  = cm + DH;
    float* b1s = cr + DH;
    float* b2s = b1s + DH;
    float* pb1s = b2s + DH;
    float* score = pb1s + DH;
    float* wsf   = score + G;

    int tid = threadIdx.x;
    int n0  = blockIdx.x * G;

    // stage packed weights: same loop serves all three 64x64 matrices
    for (int i = tid; i < 64 * 32; i += 256) {
        int j = i >> 5, c2 = i & 31;
        float2 w1v = *(const float2*)(o_w1 + j * 64 + c2 * 2);
        w1P[c2 * WPU + j] = pack2(w1v.x, w1v.y);
        float2 pw = *(const float2*)(p_w1 + j * 64 + c2 * 2);
        pw1P[c2 * WPU + j] = pack2(pw.x, pw.y);
        // for w2: j plays role of output c, c2 plays role of inner j2
        float2 w2v = *(const float2*)(o_w2 + j * 64 + c2 * 2);
        w2P[c2 * WPU + j] = pack2(w2v.x, w2v.y);
    }
    if (tid < 32) {
        pw2P[tid] = pack2(p_w2[tid * 2], p_w2[tid * 2 + 1]);
    }
    if (tid < DH) {
        b1s[tid] = o_b1[tid]; b2s[tid] = o_b2[tid];
        pb1s[tid] = p_b1[tid];
        const float invN = 1.0f / NN;
        float mean = g_hsum[tid] * invN;
        float ex2  = g_hsumsq[tid] * invN;
        float mm   = mean * no_ms[tid];
        float var  = ex2 - 2.f * mm * mean + mm * mm;
        float rinv = rsqrtf(var + 1e-5f);
        a2[tid] = no_w[tid] * rinv;
        b2v[tid] = no_b[tid] - no_w[tid] * rinv * mm;
    }
    for (int i = tid; i < G * DH; i += 256) hs[i] = g_h[(size_t)n0 * DH + i];
    __syncthreads();

    for (int i = tid; i < G * DH; i += 256) {
        int c = i & 63;
        hn[i] = fmaf(hs[i], a2[c], b2v[c]);
    }
    __syncthreads();

    // t1 = gelu(hn @ o_w1^T + b1), packed over c, 2d x 2j
    for (int i = tid; i < 384; i += 256) {
        int dp = i >> 5, jp = i & 31, d0 = dp * 2;
        u64 A00 = 0, A01 = 0, A10 = 0, A11 = 0;
        const u64* h0 = (const u64*)(hn + d0 * DH);
        const u64* h1 = (const u64*)(hn + (d0 + 1) * DH);
        #pragma unroll 8
        for (int c2 = 0; c2 < 32; c2++) {
            u64 w0 = w1P[c2 * WPU + jp], w1 = w1P[c2 * WPU + jp + 32];
            u64 hc0 = h0[c2], hc1 = h1[c2];
            A00 = fma2(hc0, w0, A00); A01 = fma2(hc0, w1, A01);
            A10 = fma2(hc1, w0, A10); A11 = fma2(hc1, w1, A11);
        }
        float lo, hi;
        unpack2(A00, lo, hi); t1[d0 * DH + jp]            = gelu_exact(lo + hi + b1s[jp]);
        unpack2(A01, lo, hi); t1[d0 * DH + jp + 32]       = gelu_exact(lo + hi + b1s[jp + 32]);
        unpack2(A10, lo, hi); t1[(d0 + 1) * DH + jp]      = gelu_exact(lo + hi + b1s[jp]);
        unpack2(A11, lo, hi); t1[(d0 + 1) * DH + jp + 32] = gelu_exact(lo + hi + b1s[jp + 32]);
    }
    __syncthreads();

    // h2 = hs + t1 @ o_w2^T + b2, packed over j, 2d x 2c
    for (int i = tid; i < 384; i += 256) {
        int dp = i >> 5, cp = i & 31, d0 = dp * 2;
        u64 A00 = 0, A01 = 0, A10 = 0, A11 = 0;
        const u64* t0 = (const u64*)(t1 + d0 * DH);
        const u64* t1r = (const u64*)(t1 + (d0 + 1) * DH);
        #pragma unroll 8
        for (int j2 = 0; j2 < 32; j2++) {
            u64 w0 = w2P[j2 * WPU + cp], w1 = w2P[j2 * WPU + cp + 32];
            u64 tc0 = t0[j2], tc1 = t1r[j2];
            A00 = fma2(tc0, w0, A00); A01 = fma2(tc0, w1, A01);
            A10 = fma2(tc1, w0, A10); A11 = fma2(tc1, w1, A11);
        }
        float lo, hi;
        unpack2(A00, lo, hi); h2[d0 * DH + cp]            = hs[d0 * DH + cp] + lo + hi + b2s[cp];
        unpack2(A01, lo, hi); h2[d0 * DH + cp + 32]       = hs[d0 * DH + cp + 32] + lo + hi + b2s[cp + 32];
        unpack2(A10, lo, hi); h2[(d0 + 1) * DH + cp]      = hs[(d0 + 1) * DH + cp] + lo + hi + b2s[cp];
        unpack2(A11, lo, hi); h2[(d0 + 1) * DH + cp + 32] = hs[(d0 + 1) * DH + cp + 32] + lo + hi + b2s[cp + 32];
    }
    __syncthreads();

    if (tid < DH) {
        int c = tid;
        float m = 0.f;
        #pragma unroll
        for (int d = 0; d < G; d++) m += h2[d * DH + c];
        m *= (1.0f / G);
        float mm = m * pn_ms[c];
        float vv = 0.f;
        #pragma unroll
        for (int d = 0; d < G; d++) { float t = h2[d * DH + c] - mm; vv += t * t; }
        vv *= (1.0f / G);
        cm[c] = mm;
        cr[c] = pn_w[c] * rsqrtf(vv + 1e-5f);
    }
    __syncthreads();

    for (int i = tid; i < G * DH; i += 256) {
        int c = i & 63;
        hn[i] = fmaf(h2[i] - cm[c], cr[c], pn_b[c]);
    }
    __syncthreads();

    // t2 = gelu(hn @ p_w1^T + pb1), packed over c
    for (int i = tid; i < 384; i += 256) {
        int dp = i >> 5, jp = i & 31, d0 = dp * 2;
        u64 A00 = 0, A01 = 0, A10 = 0, A11 = 0;
        const u64* h0 = (const u64*)(hn + d0 * DH);
        const u64* h1 = (const u64*)(hn + (d0 + 1) * DH);
        #pragma unroll 8
        for (int c2 = 0; c2 < 32; c2++) {
            u64 w0 = pw1P[c2 * WPU + jp], w1 = pw1P[c2 * WPU + jp + 32];
            u64 hc0 = h0[c2], hc1 = h1[c2];
            A00 = fma2(hc0, w0, A00); A01 = fma2(hc0, w1, A01);
            A10 = fma2(hc1, w0, A10); A11 = fma2(hc1, w1, A11);
        }
        float lo, hi;
        unpack2(A00, lo, hi); t1[d0 * DH + jp]            = gelu_exact(lo + hi + pb1s[jp]);
        unpack2(A01, lo, hi); t1[d0 * DH + jp + 32]       = gelu_exact(lo + hi + pb1s[jp + 32]);
        unpack2(A10, lo, hi); t1[(d0 + 1) * DH + jp]      = gelu_exact(lo + hi + pb1s[jp]);
        unpack2(A11, lo, hi); t1[(d0 + 1) * DH + jp + 32] = gelu_exact(lo + hi + pb1s[jp + 32]);
    }
    __syncthreads();

    if (tid < G) {
        const u64* tr = (const u64*)(t1 + tid * DH);
        u64 A = 0;
        #pragma unroll 8
        for (int j2 = 0; j2 < 32; j2++) A = fma2(tr[j2], pw2P[j2], A);
        float lo, hi;
        unpack2(A, lo, hi);
        score[tid] = lo + hi + p_b2[0];
    }
    __syncthreads();

    if (tid == 0) {
        float m = score[0];
        #pragma unroll
        for (int d = 1; d < G; d++) m = fmaxf(m, score[d]);
        float sum = 0.f;
        #pragma unroll
        for (int d = 0; d < G; d++) { wsf[d] = expf(score[d] - m); sum += wsf[d]; }
        float inv = 1.0f / (sum + 1e-16f);
        #pragma unroll
        for (int d = 0; d < G; d++) wsf[d] *= inv;
    }
    __syncthreads();

    if (tid < DIN) {
        float acc = 0.f;
        #pragma unroll
        for (int d = 0; d < G; d++)
            acc = fmaf(wsf[d], x[(size_t)(n0 + d) * DIN + tid], acc);
        out[blockIdx.x * DIN + tid] = acc;
    }
}

// ---------------- launch -----------------------------------------------------
extern "C" void kernel_launch(void* const* d_in, const int* in_sizes, int n_in,
                              void* d_out, int out_size) {
    const float* x     = (const float*)d_in[0];
    const float* nq_w  = (const float*)d_in[4];
    const float* nq_b  = (const float*)d_in[5];
    const float* nq_ms = (const float*)d_in[6];
    const float* wq    = (const float*)d_in[7];
    const float* bq    = (const float*)d_in[8];
    const float* wk    = (const float*)d_in[9];
    const float* bk    = (const float*)d_in[10];
    const float* wv    = (const float*)d_in[11];
    const float* bv    = (const float*)d_in[12];
    const float* no_w  = (const float*)d_in[13];
    const float* no_b  = (const float*)d_in[14];
    const float* no_ms = (const float*)d_in[15];
    const float* o_w1  = (const float*)d_in[16];
    const float* o_b1  = (const float*)d_in[17];
    const float* o_w2  = (const float*)d_in[18];
    const float* o_b2  = (const float*)d_in[19];
    const float* pn_w  = (const float*)d_in[20];
    const float* pn_b  = (const float*)d_in[21];
    const float* pn_ms = (const float*)d_in[22];
    const float* p_w1  = (const float*)d_in[23];
    const float* p_b1  = (const float*)d_in[24];
    const float* p_w2  = (const float*)d_in[25];
    const float* p_b2  = (const float*)d_in[26];
    float* out = (float*)d_out;

    const int smem_qkv = 512 + 2 * ATILE + 2 * BTILE;                         // 104,960 B
    const int smem_fin = (3 * 32 * WPU + 32) * 8 + (4 * G * DH + 7 * DH + 2 * G) * 4; // ~76 KB
    cudaFuncSetAttribute(k_qkv,   cudaFuncAttributeMaxDynamicSharedMemorySize, smem_qkv);
    cudaFuncSetAttribute(k_final, cudaFuncAttributeMaxDynamicSharedMemorySize, smem_fin);

    k_xstats<<<96, 256>>>(x);
    k_xnorm<<<60, 256>>>(x, nq_w, nq_b, nq_ms, wq, wk, wv);
    k_qkv<<<dim3(48, 24), 256, smem_qkv>>>(bq, bk, bv);
    k_attn<<<2048, 192>>>();
    k_hstats<<<96, 256>>>();
    k_final<<<256, 256, smem_fin>>>(x, no_w, no_b, no_ms,
                                    o_w1, o_b1, o_w2, o_b2,
                                    pn_w, pn_b, pn_ms,
                                    p_w1, p_b1, p_w2, p_b2, out);
}

// round 12
// speedup vs baseline: 1.3021x; 1.0494x over previous
#include <cuda_runtime.h>
#include <cuda_bf16.h>
#include <math.h>
#include <string.h>

#define NN   6144
#define G    24
#define DIN  128
#define DH   64
#define NH   8
#define QKV_W 1536

typedef unsigned long long u64;
typedef unsigned int u32;

// ---------------- device scratch --------------------------------------------
__device__ float g_qkv[NN * QKV_W];
__device__ float g_h[NN * DH];
__device__ unsigned short g_xhi[NN * DIN];
__device__ unsigned short g_xlo[NN * DIN];
__device__ unsigned short g_whi[QKV_W * DIN];
__device__ unsigned short g_wlo[QKV_W * DIN];
__device__ float g_xs_part[96 * DIN];
__device__ float g_xq_part[96 * DIN];
__device__ float g_hsum[DH];
__device__ float g_hsumsq[DH];

// ---------------- PTX helpers -----------------------------------------------
__device__ __forceinline__ u32 smem_u32(const void* p) {
    u32 a;
    asm("{ .reg .u64 t; cvta.to.shared.u64 t, %1; cvt.u32.u64 %0, t; }"
        : "=r"(a) : "l"(p));
    return a;
}
__device__ __forceinline__ void ldsm_x4(u32& r0, u32& r1, u32& r2, u32& r3, u32 addr) {
    asm volatile("ldmatrix.sync.aligned.m8n8.x4.shared.b16 {%0,%1,%2,%3}, [%4];"
                 : "=r"(r0), "=r"(r1), "=r"(r2), "=r"(r3) : "r"(addr));
}
__device__ __forceinline__ void ldsm_x2(u32& r0, u32& r1, u32 addr) {
    asm volatile("ldmatrix.sync.aligned.m8n8.x2.shared.b16 {%0,%1}, [%2];"
                 : "=r"(r0), "=r"(r1) : "r"(addr));
}
__device__ __forceinline__ void mma_bf16(float* d, const u32* a, const u32* b) {
    asm volatile(
        "mma.sync.aligned.m16n8k16.row.col.f32.bf16.bf16.f32 "
        "{%0,%1,%2,%3},{%4,%5,%6,%7},{%8,%9},{%0,%1,%2,%3};"
        : "+f"(d[0]), "+f"(d[1]), "+f"(d[2]), "+f"(d[3])
        : "r"(a[0]), "r"(a[1]), "r"(a[2]), "r"(a[3]), "r"(b[0]), "r"(b[1]));
}
__device__ __forceinline__ u64 pack2(float lo, float hi) {
    u64 r; asm("mov.b64 %0,{%1,%2};" : "=l"(r) : "f"(lo), "f"(hi)); return r;
}
__device__ __forceinline__ u64 fma2(u64 a, u64 b, u64 c) {
    u64 d; asm("fma.rn.f32x2 %0,%1,%2,%3;" : "=l"(d) : "l"(a), "l"(b), "l"(c)); return d;
}
__device__ __forceinline__ void unpack2(u64 v, float& lo, float& hi) {
    asm("mov.b64 {%0,%1},%2;" : "=f"(lo), "=f"(hi) : "l"(v));
}

__device__ __forceinline__ unsigned short bf16bits(float v) {
    __nv_bfloat16 b = __float2bfloat16(v);
    unsigned short s; memcpy(&s, &b, 2); return s;
}
__device__ __forceinline__ float bf16val(float v) {
    return __bfloat162float(__float2bfloat16(v));
}

// ---------------- K1: x stats partials --------------------------------------
__global__ void __launch_bounds__(256)
k_xstats(const float* __restrict__ x) {
    __shared__ float smS[8 * 128], smQ[8 * 128];
    int t  = threadIdx.x;
    int c4 = t & 31;
    int rs = t >> 5;
    int r0 = blockIdx.x * 64;

    const float4* xg = (const float4*)x;
    float4 s = make_float4(0.f, 0.f, 0.f, 0.f);
    float4 q = make_float4(0.f, 0.f, 0.f, 0.f);
    #pragma unroll
    for (int r = rs; r < 64; r += 8) {
        float4 v = xg[(size_t)(r0 + r) * 32 + c4];
        s.x += v.x; s.y += v.y; s.z += v.z; s.w += v.w;
        q.x += v.x * v.x; q.y += v.y * v.y; q.z += v.z * v.z; q.w += v.w * v.w;
    }
    ((float4*)smS)[rs * 32 + c4] = s;
    ((float4*)smQ)[rs * 32 + c4] = q;
    __syncthreads();
    if (t < 128) {
        float ss = 0.f, qq = 0.f;
        #pragma unroll
        for (int j = 0; j < 8; j++) { ss += smS[j * 128 + t]; qq += smQ[j * 128 + t]; }
        g_xs_part[blockIdx.x * 128 + t] = ss;
        g_xq_part[blockIdx.x * 128 + t] = qq;
    }
}

// ---------------- K2: normalize x -> bf16 hi/lo; W -> bf16 hi/lo; h init ----
__global__ void __launch_bounds__(256)
k_xnorm(const float* __restrict__ x,
        const float* __restrict__ nq_w, const float* __restrict__ nq_b,
        const float* __restrict__ nq_ms,
        const float* __restrict__ wq, const float* __restrict__ wk,
        const float* __restrict__ wv) {
    int tid = threadIdx.x;
    int b   = blockIdx.x;

    if (b == 0 && tid < DH) { g_hsum[tid] = 0.f; g_hsumsq[tid] = 0.f; }

    uint2* xh = (uint2*)g_xhi;
    uint2* xl = (uint2*)g_xlo;
    uint2* wh = (uint2*)g_whi;
    uint2* wl = (uint2*)g_wlo;

    if (b < 48) {
        __shared__ float As[128], Bs[128];
        if (tid < 128) {
            float ss = 0.f, qq = 0.f;
            #pragma unroll 8
            for (int p = 0; p < 96; p++) {
                ss += g_xs_part[p * 128 + tid];
                qq += g_xq_part[p * 128 + tid];
            }
            const float invN = 1.0f / NN;
            float mean = ss * invN;
            float ex2  = qq * invN;
            float mm   = mean * nq_ms[tid];
            float var  = ex2 - 2.f * mm * mean + mm * mm;
            float rinv = rsqrtf(var + 1e-5f);
            As[tid] = nq_w[tid] * rinv;
            Bs[tid] = nq_b[tid] - nq_w[tid] * rinv * mm;
        }
        __syncthreads();
        int r0 = b * 128;
        const float4* xg = (const float4*)x;
        for (int i = tid; i < 128 * 32; i += 256) {
            int row = i >> 5, c4 = i & 31, c = c4 * 4;
            float4 v = xg[(size_t)(r0 + row) * 32 + c4];
            float f[4];
            f[0] = fmaf(v.x, As[c],     Bs[c]);
            f[1] = fmaf(v.y, As[c + 1], Bs[c + 1]);
            f[2] = fmaf(v.z, As[c + 2], Bs[c + 2]);
            f[3] = fmaf(v.w, As[c + 3], Bs[c + 3]);
            unsigned short h[4], l[4];
            #pragma unroll
            for (int j = 0; j < 4; j++) {
                h[j] = bf16bits(f[j]);
                l[j] = bf16bits(f[j] - bf16val(f[j]));
            }
            uint2 uh, ul;
            uh.x = (u32)h[0] | ((u32)h[1] << 16); uh.y = (u32)h[2] | ((u32)h[3] << 16);
            ul.x = (u32)l[0] | ((u32)l[1] << 16); ul.y = (u32)l[2] | ((u32)l[3] << 16);
            size_t idx = (size_t)(r0 + row) * 32 + c4;
            xh[idx] = uh; xl[idx] = ul;
        }
        // residual init: g_h = x[:, :64] + x[:, 64:]
        float4* h4 = (float4*)g_h;
        for (int i = tid; i < 128 * 16; i += 256) {
            int row = i >> 4, c4 = i & 15;
            float4 xa = xg[(size_t)(r0 + row) * 32 + c4];
            float4 xb = xg[(size_t)(r0 + row) * 32 + 16 + c4];
            h4[(size_t)(r0 + row) * 16 + c4] =
                make_float4(xa.x + xb.x, xa.y + xb.y, xa.z + xb.z, xa.w + xb.w);
        }
    } else {
        int wr0 = (b - 48) * 128;
        for (int i = tid; i < 128 * 32; i += 256) {
            int row = i >> 5, c4 = i & 31;
            int gidx = wr0 + row;
            int mat = gidx >> 9, lr = gidx & 511;
            const float4* src = (const float4*)(mat == 0 ? wq : (mat == 1 ? wk : wv));
            float4 v = src[(size_t)lr * 32 + c4];
            float f[4] = {v.x, v.y, v.z, v.w};
            unsigned short h[4], l[4];
            #pragma unroll
            for (int j = 0; j < 4; j++) {
                h[j] = bf16bits(f[j]);
                l[j] = bf16bits(f[j] - bf16val(f[j]));
            }
            uint2 uh, ul;
            uh.x = (u32)h[0] | ((u32)h[1] << 16); uh.y = (u32)h[2] | ((u32)h[3] << 16);
            ul.x = (u32)l[0] | ((u32)l[1] << 16); ul.y = (u32)l[2] | ((u32)l[3] << 16);
            size_t idx = (size_t)gidx * 32 + c4;
            wh[idx] = uh; wl[idx] = ul;
        }
    }
}

// ---------------- K3: QKV GEMM via mma.sync bf16 split (hi+lo) --------------
#define ROWB 272
#define ATILE (128 * ROWB)
#define BTILE (64 * ROWB)
__global__ void __launch_bounds__(256, 2)
k_qkv(const float* __restrict__ bq, const float* __restrict__ bk,
      const float* __restrict__ bv) {
    extern __shared__ char smc[];
    float* bias_s = (float*)smc;
    char* aH = smc + 512;
    char* aL = aH + ATILE;
    char* bH = aL + ATILE;
    char* bL = bH + BTILE;

    int tid = threadIdx.x;
    int m0 = blockIdx.x * 128;
    int oc = blockIdx.y * 64;
    int mat = oc >> 9, o0 = oc & 511;
    const float* bias = mat == 0 ? bq : (mat == 1 ? bk : bv);
    if (tid < 64) bias_s[tid] = bias[o0 + tid];

    const uint2* xh = (const uint2*)g_xhi;
    const uint2* xl = (const uint2*)g_xlo;
    const uint2* wh = (const uint2*)g_whi;
    const uint2* wl = (const uint2*)g_wlo;

    #pragma unroll
    for (int i = tid; i < 4096; i += 256) {
        int row = i >> 5, c4 = i & 31;
        int so = row * ROWB + c4 * 8;
        size_t ax = (size_t)(m0 + row) * 32 + c4;
        *(uint2*)(aH + so) = xh[ax];
        *(uint2*)(aL + so) = xl[ax];
    }
    #pragma unroll
    for (int i = tid; i < 2048; i += 256) {
        int row = i >> 5, c4 = i & 31;
        int so = row * ROWB + c4 * 8;
        size_t bx = (size_t)(oc + row) * 32 + c4;
        *(uint2*)(bH + so) = wh[bx];
        *(uint2*)(bL + so) = wl[bx];
    }
    __syncthreads();

    u32 sb = smem_u32(smc);
    u32 aHb = sb + 512, aLb = aHb + ATILE, bHb = aLb + ATILE, bLb = bHb + BTILE;

    int t   = tid & 31;
    int wid = tid >> 5;
    int wm = (wid & 3) * 32;
    int wn = (wid >> 2) * 32;
    int rowA = ((t >> 3) & 1) * 8 + (t & 7);
    int kofA = (t >> 4) * 8;
    int rowB = (t & 7);
    int kofB = ((t >> 3) & 1) * 8;

    float acc[2][4][4];
    #pragma unroll
    for (int mf = 0; mf < 2; mf++)
        #pragma unroll
        for (int nf = 0; nf < 4; nf++)
            #pragma unroll
            for (int j = 0; j < 4; j++) acc[mf][nf][j] = 0.f;

    for (int k = 0; k < 128; k += 16) {
        u32 ah[2][4], al[2][4], bh[4][2], bl[4][2];
        #pragma unroll
        for (int mf = 0; mf < 2; mf++) {
            u32 off = (u32)((wm + mf * 16 + rowA) * ROWB + (k + kofA) * 2);
            ldsm_x4(ah[mf][0], ah[mf][1], ah[mf][2], ah[mf][3], aHb + off);
            ldsm_x4(al[mf][0], al[mf][1], al[mf][2], al[mf][3], aLb + off);
        }
        #pragma unroll
        for (int nf = 0; nf < 4; nf++) {
            u32 off = (u32)((wn + nf * 8 + rowB) * ROWB + (k + kofB) * 2);
            ldsm_x2(bh[nf][0], bh[nf][1], bHb + off);
            ldsm_x2(bl[nf][0], bl[nf][1], bLb + off);
        }
        #pragma unroll
        for (int mf = 0; mf < 2; mf++)
            #pragma unroll
            for (int nf = 0; nf < 4; nf++) {
                mma_bf16(acc[mf][nf], ah[mf], bh[nf]);
                mma_bf16(acc[mf][nf], ah[mf], bl[nf]);
                mma_bf16(acc[mf][nf], al[mf], bh[nf]);
            }
    }

    int tq = t >> 2, tr = t & 3;
    #pragma unroll
    for (int mf = 0; mf < 2; mf++) {
        int m = m0 + wm + mf * 16 + tq;
        #pragma unroll
        for (int nf = 0; nf < 4; nf++) {
            int ln = wn + nf * 8 + tr * 2;
            float b0 = bias_s[ln], b1 = bias_s[ln + 1];
            float2 v0 = make_float2(acc[mf][nf][0] + b0, acc[mf][nf][1] + b1);
            float2 v1 = make_float2(acc[mf][nf][2] + b0, acc[mf][nf][3] + b1);
            *(float2*)(g_qkv + (size_t)m * QKV_W + oc + ln) = v0;
            *(float2*)(g_qkv + (size_t)(m + 8) * QKV_W + oc + ln) = v1;
        }
    }
}

// ---------------- K4: attention, 2 heads of one set per CTA -----------------
// grid 1024 = 256 sets x 4 head-pairs. 192 threads. smem ~42.8KB -> 5 CTAs/SM.
// Phases: load both heads -> logits (192 threads: 96 per head) ->
//         softmax (48 threads) -> aggregate (96 threads, both heads summed
//         into the same registers -> one atomicAdd set; halves atomics).
#define PBUF 1192   // float4 units per head: q 408 | kt 400 | v 384
__global__ void __launch_bounds__(192, 5)
k_attn() {
    __shared__ float4 buf[2][PBUF];
    __shared__ __align__(16) float alphaT[2][24 * 24];   // [s][d]

    int tid = threadIdx.x;
    int set = blockIdx.x >> 2;
    int h0  = (blockIdx.x & 3) << 1;     // heads h0, h0+1
    int n0  = set * G;

    const float4* src4 = (const float4*)g_qkv + (size_t)n0 * 384;
    #pragma unroll
    for (int p = 0; p < 2; p++) {
        float4* q4h = buf[p];
        float4* kt4 = buf[p] + 408;
        float4* v4h = buf[p] + 808;
        int h = h0 + p;
        #pragma unroll
        for (int i = tid; i < 24 * 16; i += 192) {
            int n = i >> 4, c4 = i & 15;
            q4h[n * 17 + c4] = src4[n * 384 + h * 16 + c4];
            v4h[n * 16 + c4] = src4[n * 384 + 256 + h * 16 + c4];
            kt4[c4 * 25 + n] = src4[n * 384 + 128 + h * 16 + c4];
        }
    }
    __syncthreads();

    // logits: 192 threads = 2 heads x 96 (each: 2 d x 3 s)
    {
        int p = tid >= 96;
        int r = tid - p * 96;
        const ulonglong2* q8 = (const ulonglong2*)buf[p];
        const ulonglong2* k8 = (const ulonglong2*)(buf[p] + 408);
        float* aT = alphaT[p];
        int d0 = (r >> 3) * 2;
        int sg = r & 7;
        u64 a00 = 0, a01 = 0, a02 = 0, a10 = 0, a11 = 0, a12 = 0;
        #pragma unroll
        for (int j = 0; j < 16; j++) {
            ulonglong2 q0 = q8[d0 * 17 + j];
            ulonglong2 q1 = q8[(d0 + 1) * 17 + j];
            ulonglong2 k0 = k8[j * 25 + sg * 3];
            ulonglong2 k1 = k8[j * 25 + sg * 3 + 1];
            ulonglong2 k2 = k8[j * 25 + sg * 3 + 2];
            a00 = fma2(q0.x, k0.x, a00); a00 = fma2(q0.y, k0.y, a00);
            a01 = fma2(q0.x, k1.x, a01); a01 = fma2(q0.y, k1.y, a01);
            a02 = fma2(q0.x, k2.x, a02); a02 = fma2(q0.y, k2.y, a02);
            a10 = fma2(q1.x, k0.x, a10); a10 = fma2(q1.y, k0.y, a10);
            a11 = fma2(q1.x, k1.x, a11); a11 = fma2(q1.y, k1.y, a11);
            a12 = fma2(q1.x, k2.x, a12); a12 = fma2(q1.y, k2.y, a12);
        }
        float lo, hi;
        int s0 = sg * 3;
        unpack2(a00, lo, hi); aT[(s0 + 0) * 24 + d0]     = (lo + hi) * 0.125f;
        unpack2(a01, lo, hi); aT[(s0 + 1) * 24 + d0]     = (lo + hi) * 0.125f;
        unpack2(a02, lo, hi); aT[(s0 + 2) * 24 + d0]     = (lo + hi) * 0.125f;
        unpack2(a10, lo, hi); aT[(s0 + 0) * 24 + d0 + 1] = (lo + hi) * 0.125f;
        unpack2(a11, lo, hi); aT[(s0 + 1) * 24 + d0 + 1] = (lo + hi) * 0.125f;
        unpack2(a12, lo, hi); aT[(s0 + 2) * 24 + d0 + 1] = (lo + hi) * 0.125f;
    }
    __syncthreads();

    // softmax: 48 threads = 2 heads x 24 destinations
    if (tid < 48) {
        int p = tid / 24, d = tid - p * 24;
        float* aT = alphaT[p];
        float m = aT[d];
        #pragma unroll
        for (int s = 1; s < G; s++) m = fmaxf(m, aT[s * 24 + d]);
        float sum = 0.f;
        #pragma unroll
        for (int s = 0; s < G; s++) {
            float e = expf(aT[s * 24 + d] - m);
            aT[s * 24 + d] = e;
            sum += e;
        }
        float inv = 1.0f / (sum + 1e-16f);
        #pragma unroll
        for (int s = 0; s < G; s++) aT[s * 24 + d] *= inv;
    }
    __syncthreads();

    // aggregate: 96 threads (dg, c4); both heads summed into the same accs
    if (tid < 96) {
        int dg = tid >> 4, c4 = tid & 15, d0 = dg * 4;
        u64 acc[4][2];
        #pragma unroll
        for (int i2 = 0; i2 < 4; i2++) { acc[i2][0] = 0ull; acc[i2][1] = 0ull; }
        #pragma unroll
        for (int p = 0; p < 2; p++) {
            const ulonglong2* v8 = (const ulonglong2*)(buf[p] + 808);
            const float* aT = alphaT[p];
            #pragma unroll
            for (int s = 0; s < G; s++) {
                float4 al = *(const float4*)&aT[s * 24 + d0];
                ulonglong2 vv = v8[s * 16 + c4];
                u64 pp;
                pp = pack2(al.x, al.x); acc[0][0] = fma2(pp, vv.x, acc[0][0]); acc[0][1] = fma2(pp, vv.y, acc[0][1]);
                pp = pack2(al.y, al.y); acc[1][0] = fma2(pp, vv.x, acc[1][0]); acc[1][1] = fma2(pp, vv.y, acc[1][1]);
                pp = pack2(al.z, al.z); acc[2][0] = fma2(pp, vv.x, acc[2][0]); acc[2][1] = fma2(pp, vv.y, acc[2][1]);
                pp = pack2(al.w, al.w); acc[3][0] = fma2(pp, vv.x, acc[3][0]); acc[3][1] = fma2(pp, vv.y, acc[3][1]);
            }
        }
        #pragma unroll
        for (int i2 = 0; i2 < 4; i2++) {
            float* dst = g_h + (size_t)(n0 + d0 + i2) * DH + c4 * 4;
            float x0, x1, x2, x3;
            unpack2(acc[i2][0], x0, x1);
            unpack2(acc[i2][1], x2, x3);
            atomicAdd(dst + 0, x0 * 0.125f);
            atomicAdd(dst + 1, x1 * 0.125f);
            atomicAdd(dst + 2, x2 * 0.125f);
            atomicAdd(dst + 3, x3 * 0.125f);
        }
    }
}

// ---------------- K5: h stats (96 blocks x 64 rows) -------------------------
__global__ void __launch_bounds__(256)
k_hstats() {
    __shared__ float smS[16 * 64], smQ[16 * 64];
    int t  = threadIdx.x;
    int c4 = t & 15;
    int rs = t >> 4;
    int r0 = blockIdx.x * 64;

    const float4* h4 = (const float4*)g_h;
    float4 s = make_float4(0.f, 0.f, 0.f, 0.f);
    float4 q = make_float4(0.f, 0.f, 0.f, 0.f);
    #pragma unroll
    for (int r = rs; r < 64; r += 16) {
        float4 a = h4[(size_t)(r0 + r) * 16 + c4];
        s.x += a.x; s.y += a.y; s.z += a.z; s.w += a.w;
        q.x += a.x * a.x; q.y += a.y * a.y; q.z += a.z * a.z; q.w += a.w * a.w;
    }
    ((float4*)smS)[rs * 16 + c4] = s;
    ((float4*)smQ)[rs * 16 + c4] = q;
    __syncthreads();
    if (t < 64) {
        float ss = 0.f, qq = 0.f;
        #pragma unroll
        for (int j = 0; j < 16; j++) { ss += smS[j * 64 + t]; qq += smQ[j * 64 + t]; }
        atomicAdd(&g_hsum[t], ss);
        atomicAdd(&g_hsumsq[t], qq);
    }
}

__device__ __forceinline__ float gelu_exact(float v) {
    return 0.5f * v * (1.0f + erff(v * 0.70710678118654752f));
}

// ---------------- K6: global norm + PFF + per-set norm + score + pooling ----
#define WPU 65
__global__ void __launch_bounds__(256)
k_final(const float* __restrict__ x,
        const float* __restrict__ no_w, const float* __restrict__ no_b,
        const float* __restrict__ no_ms,
        const float* __restrict__ o_w1, const float* __restrict__ o_b1,
        const float* __restrict__ o_w2, const float* __restrict__ o_b2,
        const float* __restrict__ pn_w, const float* __restrict__ pn_b,
        const float* __restrict__ pn_ms,
        const float* __restrict__ p_w1, const float* __restrict__ p_b1,
        const float* __restrict__ p_w2, const float* __restrict__ p_b2,
        float* __restrict__ out) {
    extern __shared__ float dsm[];
    u64*  w1P  = (u64*)dsm;
    u64*  w2P  = w1P + 32 * WPU;
    u64*  pw1P = w2P + 32 * WPU;
    u64*  pw2P = pw1P + 32 * WPU;
    float* hs  = (float*)(pw2P + 32);
    float* hn  = hs + G * DH;
    float* t1  = hn + G * DH;
    float* h2  = t1 + G * DH;
    float* a2  = h2 + G * DH;
    float* b2v = a2 + DH;
    float* cm  = b2v + DH;
    float* cr  = cm + DH;
    float* b1s = cr + DH;
    float* b2s = b1s + DH;
    float* pb1s = b2s + DH;
    float* score = pb1s + DH;
    float* wsf   = score + G;

    int tid = threadIdx.x;
    int n0  = blockIdx.x * G;

    for (int i = tid; i < 64 * 32; i += 256) {
        int j = i >> 5, c2 = i & 31;
        float2 w1v = *(const float2*)(o_w1 + j * 64 + c2 * 2);
        w1P[c2 * WPU + j] = pack2(w1v.x, w1v.y);
        float2 pw = *(const float2*)(p_w1 + j * 64 + c2 * 2);
        pw1P[c2 * WPU + j] = pack2(pw.x, pw.y);
        float2 w2v = *(const float2*)(o_w2 + j * 64 + c2 * 2);
        w2P[c2 * WPU + j] = pack2(w2v.x, w2v.y);
    }
    if (tid < 32) {
        pw2P[tid] = pack2(p_w2[tid * 2], p_w2[tid * 2 + 1]);
    }
    if (tid < DH) {
        b1s[tid] = o_b1[tid]; b2s[tid] = o_b2[tid];
        pb1s[tid] = p_b1[tid];
        const float invN = 1.0f / NN;
        float mean = g_hsum[tid] * invN;
        float ex2  = g_hsumsq[tid] * invN;
        float mm   = mean * no_ms[tid];
        float var  = ex2 - 2.f * mm * mean + mm * mm;
        float rinv = rsqrtf(var + 1e-5f);
        a2[tid] = no_w[tid] * rinv;
        b2v[tid] = no_b[tid] - no_w[tid] * rinv * mm;
    }
    for (int i = tid; i < G * DH; i += 256) hs[i] = g_h[(size_t)n0 * DH + i];
    __syncthreads();

    for (int i = tid; i < G * DH; i += 256) {
        int c = i & 63;
        hn[i] = fmaf(hs[i], a2[c], b2v[c]);
    }
    __syncthreads();

    for (int i = tid; i < 384; i += 256) {
        int dp = i >> 5, jp = i & 31, d0 = dp * 2;
        u64 A00 = 0, A01 = 0, A10 = 0, A11 = 0;
        const u64* h0 = (const u64*)(hn + d0 * DH);
        const u64* h1 = (const u64*)(hn + (d0 + 1) * DH);
        #pragma unroll 8
        for (int c2 = 0; c2 < 32; c2++) {
            u64 w0 = w1P[c2 * WPU + jp], w1 = w1P[c2 * WPU + jp + 32];
            u64 hc0 = h0[c2], hc1 = h1[c2];
            A00 = fma2(hc0, w0, A00); A01 = fma2(hc0, w1, A01);
            A10 = fma2(hc1, w0, A10); A11 = fma2(hc1, w1, A11);
        }
        float lo, hi;
        unpack2(A00, lo, hi); t1[d0 * DH + jp]            = gelu_exact(lo + hi + b1s[jp]);
        unpack2(A01, lo, hi); t1[d0 * DH + jp + 32]       = gelu_exact(lo + hi + b1s[jp + 32]);
        unpack2(A10, lo, hi); t1[(d0 + 1) * DH + jp]      = gelu_exact(lo + hi + b1s[jp]);
        unpack2(A11, lo, hi); t1[(d0 + 1) * DH + jp + 32] = gelu_exact(lo + hi + b1s[jp + 32]);
    }
    __syncthreads();

    for (int i = tid; i < 384; i += 256) {
        int dp = i >> 5, cp = i & 31, d0 = dp * 2;
        u64 A00 = 0, A01 = 0, A10 = 0, A11 = 0;
        const u64* t0 = (const u64*)(t1 + d0 * DH);
        const u64* t1r = (const u64*)(t1 + (d0 + 1) * DH);
        #pragma unroll 8
        for (int j2 = 0; j2 < 32; j2++) {
            u64 w0 = w2P[j2 * WPU + cp], w1 = w2P[j2 * WPU + cp + 32];
            u64 tc0 = t0[j2], tc1 = t1r[j2];
            A00 = fma2(tc0, w0, A00); A01 = fma2(tc0, w1, A01);
            A10 = fma2(tc1, w0, A10); A11 = fma2(tc1, w1, A11);
        }
        float lo, hi;
        unpack2(A00, lo, hi); h2[d0 * DH + cp]            = hs[d0 * DH + cp] + lo + hi + b2s[cp];
        unpack2(A01, lo, hi); h2[d0 * DH + cp + 32]       = hs[d0 * DH + cp + 32] + lo + hi + b2s[cp + 32];
        unpack2(A10, lo, hi); h2[(d0 + 1) * DH + cp]      = hs[(d0 + 1) * DH + cp] + lo + hi + b2s[cp];
        unpack2(A11, lo, hi); h2[(d0 + 1) * DH + cp + 32] = hs[(d0 + 1) * DH + cp + 32] + lo + hi + b2s[cp + 32];
    }
    __syncthreads();

    if (tid < DH) {
        int c = tid;
        float m = 0.f;
        #pragma unroll
        for (int d = 0; d < G; d++) m += h2[d * DH + c];
        m *= (1.0f / G);
        float mm = m * pn_ms[c];
        float vv = 0.f;
        #pragma unroll
        for (int d = 0; d < G; d++) { float t = h2[d * DH + c] - mm; vv += t * t; }
        vv *= (1.0f / G);
        cm[c] = mm;
        cr[c] = pn_w[c] * rsqrtf(vv + 1e-5f);
    }
    __syncthreads();

    for (int i = tid; i < G * DH; i += 256) {
        int c = i & 63;
        hn[i] = fmaf(h2[i] - cm[c], cr[c], pn_b[c]);
    }
    __syncthreads();

    for (int i = tid; i < 384; i += 256) {
        int dp = i >> 5, jp = i & 31, d0 = dp * 2;
        u64 A00 = 0, A01 = 0, A10 = 0, A11 = 0;
        const u64* h0 = (const u64*)(hn + d0 * DH);
        const u64* h1 = (const u64*)(hn + (d0 + 1) * DH);
        #pragma unroll 8
        for (int c2 = 0; c2 < 32; c2++) {
            u64 w0 = pw1P[c2 * WPU + jp], w1 = pw1P[c2 * WPU + jp + 32];
            u64 hc0 = h0[c2], hc1 = h1[c2];
            A00 = fma2(hc0, w0, A00); A01 = fma2(hc0, w1, A01);
            A10 = fma2(hc1, w0, A10); A11 = fma2(hc1, w1, A11);
        }
        float lo, hi;
        unpack2(A00, lo, hi); t1[d0 * DH + jp]            = gelu_exact(lo + hi + pb1s[jp]);
        unpack2(A01, lo, hi); t1[d0 * DH + jp + 32]       = gelu_exact(lo + hi + pb1s[jp + 32]);
        unpack2(A10, lo, hi); t1[(d0 + 1) * DH + jp]      = gelu_exact(lo + hi + pb1s[jp]);
        unpack2(A11, lo, hi); t1[(d0 + 1) * DH + jp + 32] = gelu_exact(lo + hi + pb1s[jp + 32]);
    }
    __syncthreads();

    if (tid < G) {
        const u64* tr = (const u64*)(t1 + tid * DH);
        u64 A = 0;
        #pragma unroll 8
        for (int j2 = 0; j2 < 32; j2++) A = fma2(tr[j2], pw2P[j2], A);
        float lo, hi;
        unpack2(A, lo, hi);
        score[tid] = lo + hi + p_b2[0];
    }
    __syncthreads();

    if (tid == 0) {
        float m = score[0];
        #pragma unroll
        for (int d = 1; d < G; d++) m = fmaxf(m, score[d]);
        float sum = 0.f;
        #pragma unroll
        for (int d = 0; d < G; d++) { wsf[d] = expf(score[d] - m); sum += wsf[d]; }
        float inv = 1.0f / (sum + 1e-16f);
        #pragma unroll
        for (int d = 0; d < G; d++) wsf[d] *= inv;
    }
    __syncthreads();

    if (tid < DIN) {
        float acc = 0.f;
        #pragma unroll
        for (int d = 0; d < G; d++)
            acc = fmaf(wsf[d], x[(size_t)(n0 + d) * DIN + tid], acc);
        out[blockIdx.x * DIN + tid] = acc;
    }
}

// ---------------- launch -----------------------------------------------------
extern "C" void kernel_launch(void* const* d_in, const int* in_sizes, int n_in,
                              void* d_out, int out_size) {
    const float* x     = (const float*)d_in[0];
    const float* nq_w  = (const float*)d_in[4];
    const float* nq_b  = (const float*)d_in[5];
    const float* nq_ms = (const float*)d_in[6];
    const float* wq    = (const float*)d_in[7];
    const float* bq    = (const float*)d_in[8];
    const float* wk    = (const float*)d_in[9];
    const float* bk    = (const float*)d_in[10];
    const float* wv    = (const float*)d_in[11];
    const float* bv    = (const float*)d_in[12];
    const float* no_w  = (const float*)d_in[13];
    const float* no_b  = (const float*)d_in[14];
    const float* no_ms = (const float*)d_in[15];
    const float* o_w1  = (const float*)d_in[16];
    const float* o_b1  = (const float*)d_in[17];
    const float* o_w2  = (const float*)d_in[18];
    const float* o_b2  = (const float*)d_in[19];
    const float* pn_w  = (const float*)d_in[20];
    const float* pn_b  = (const float*)d_in[21];
    const float* pn_ms = (const float*)d_in[22];
    const float* p_w1  = (const float*)d_in[23];
    const float* p_b1  = (const float*)d_in[24];
    const float* p_w2  = (const float*)d_in[25];
    const float* p_b2  = (const float*)d_in[26];
    float* out = (float*)d_out;

    const int smem_qkv = 512 + 2 * ATILE + 2 * BTILE;
    const int smem_fin = (3 * 32 * WPU + 32) * 8 + (4 * G * DH + 7 * DH + 2 * G) * 4;
    cudaFuncSetAttribute(k_qkv,   cudaFuncAttributeMaxDynamicSharedMemorySize, smem_qkv);
    cudaFuncSetAttribute(k_final, cudaFuncAttributeMaxDynamicSharedMemorySize, smem_fin);

    k_xstats<<<96, 256>>>(x);
    k_xnorm<<<60, 256>>>(x, nq_w, nq_b, nq_ms, wq, wk, wv);
    k_qkv<<<dim3(48, 24), 256, smem_qkv>>>(bq, bk, bv);
    k_attn<<<1024, 192>>>();
    k_hstats<<<96, 256>>>();
    k_final<<<256, 256, smem_fin>>>(x, no_w, no_b, no_ms,
                                    o_w1, o_b1, o_w2, o_b2,
                                    pn_w, pn_b, pn_ms,
                                    p_w1, p_b1, p_w2, p_b2, out);
}

// round 13
// speedup vs baseline: 1.3060x; 1.0030x over previous
#include <cuda_runtime.h>
#include <cuda_bf16.h>
#include <cuda_fp16.h>
#include <math.h>
#include <string.h>

#define NN   6144
#define G    24
#define DIN  128
#define DH   64
#define NH   8
#define QKV_W 1536

typedef unsigned long long u64;
typedef unsigned int u32;

// ---------------- device scratch --------------------------------------------
__device__ __half g_qkv[NN * QKV_W];           // 18.9 MB fp16 qkv
__device__ float g_h[NN * DH];
__device__ unsigned short g_xhi[NN * DIN];
__device__ unsigned short g_xlo[NN * DIN];
__device__ unsigned short g_whi[QKV_W * DIN];
__device__ unsigned short g_wlo[QKV_W * DIN];
__device__ float g_xs_part[96 * DIN];
__device__ float g_xq_part[96 * DIN];
__device__ float g_hsum[DH];
__device__ float g_hsumsq[DH];

// ---------------- PTX helpers -----------------------------------------------
__device__ __forceinline__ u32 smem_u32(const void* p) {
    u32 a;
    asm("{ .reg .u64 t; cvta.to.shared.u64 t, %1; cvt.u32.u64 %0, t; }"
        : "=r"(a) : "l"(p));
    return a;
}
__device__ __forceinline__ void ldsm_x4(u32& r0, u32& r1, u32& r2, u32& r3, u32 addr) {
    asm volatile("ldmatrix.sync.aligned.m8n8.x4.shared.b16 {%0,%1,%2,%3}, [%4];"
                 : "=r"(r0), "=r"(r1), "=r"(r2), "=r"(r3) : "r"(addr));
}
__device__ __forceinline__ void ldsm_x2(u32& r0, u32& r1, u32 addr) {
    asm volatile("ldmatrix.sync.aligned.m8n8.x2.shared.b16 {%0,%1}, [%2];"
                 : "=r"(r0), "=r"(r1) : "r"(addr));
}
__device__ __forceinline__ void mma_bf16(float* d, const u32* a, const u32* b) {
    asm volatile(
        "mma.sync.aligned.m16n8k16.row.col.f32.bf16.bf16.f32 "
        "{%0,%1,%2,%3},{%4,%5,%6,%7},{%8,%9},{%0,%1,%2,%3};"
        : "+f"(d[0]), "+f"(d[1]), "+f"(d[2]), "+f"(d[3])
        : "r"(a[0]), "r"(a[1]), "r"(a[2]), "r"(a[3]), "r"(b[0]), "r"(b[1]));
}
__device__ __forceinline__ u64 pack2(float lo, float hi) {
    u64 r; asm("mov.b64 %0,{%1,%2};" : "=l"(r) : "f"(lo), "f"(hi)); return r;
}
__device__ __forceinline__ u64 fma2(u64 a, u64 b, u64 c) {
    u64 d; asm("fma.rn.f32x2 %0,%1,%2,%3;" : "=l"(d) : "l"(a), "l"(b), "l"(c)); return d;
}
__device__ __forceinline__ void unpack2(u64 v, float& lo, float& hi) {
    asm("mov.b64 {%0,%1},%2;" : "=f"(lo), "=f"(hi) : "l"(v));
}
__device__ __forceinline__ void cvt8(uint4 u, float4& a, float4& b) {
    float2 p0 = __half22float2(*(__half2*)&u.x);
    float2 p1 = __half22float2(*(__half2*)&u.y);
    float2 p2 = __half22float2(*(__half2*)&u.z);
    float2 p3 = __half22float2(*(__half2*)&u.w);
    a = make_float4(p0.x, p0.y, p1.x, p1.y);
    b = make_float4(p2.x, p2.y, p3.x, p3.y);
}

__device__ __forceinline__ unsigned short bf16bits(float v) {
    __nv_bfloat16 b = __float2bfloat16(v);
    unsigned short s; memcpy(&s, &b, 2); return s;
}
__device__ __forceinline__ float bf16val(float v) {
    return __bfloat162float(__float2bfloat16(v));
}

// ---------------- K1: x stats partials --------------------------------------
__global__ void __launch_bounds__(256)
k_xstats(const float* __restrict__ x) {
    __shared__ float smS[8 * 128], smQ[8 * 128];
    int t  = threadIdx.x;
    int c4 = t & 31;
    int rs = t >> 5;
    int r0 = blockIdx.x * 64;

    const float4* xg = (const float4*)x;
    float4 s = make_float4(0.f, 0.f, 0.f, 0.f);
    float4 q = make_float4(0.f, 0.f, 0.f, 0.f);
    #pragma unroll
    for (int r = rs; r < 64; r += 8) {
        float4 v = xg[(size_t)(r0 + r) * 32 + c4];
        s.x += v.x; s.y += v.y; s.z += v.z; s.w += v.w;
        q.x += v.x * v.x; q.y += v.y * v.y; q.z += v.z * v.z; q.w += v.w * v.w;
    }
    ((float4*)smS)[rs * 32 + c4] = s;
    ((float4*)smQ)[rs * 32 + c4] = q;
    __syncthreads();
    if (t < 128) {
        float ss = 0.f, qq = 0.f;
        #pragma unroll
        for (int j = 0; j < 8; j++) { ss += smS[j * 128 + t]; qq += smQ[j * 128 + t]; }
        g_xs_part[blockIdx.x * 128 + t] = ss;
        g_xq_part[blockIdx.x * 128 + t] = qq;
    }
}

// ---------------- K2: normalize x -> bf16 hi/lo; W -> bf16 hi/lo; h init ----
__global__ void __launch_bounds__(256)
k_xnorm(const float* __restrict__ x,
        const float* __restrict__ nq_w, const float* __restrict__ nq_b,
        const float* __restrict__ nq_ms,
        const float* __restrict__ wq, const float* __restrict__ wk,
        const float* __restrict__ wv) {
    int tid = threadIdx.x;
    int b   = blockIdx.x;

    if (b == 0 && tid < DH) { g_hsum[tid] = 0.f; g_hsumsq[tid] = 0.f; }

    uint2* xh = (uint2*)g_xhi;
    uint2* xl = (uint2*)g_xlo;
    uint2* wh = (uint2*)g_whi;
    uint2* wl = (uint2*)g_wlo;

    if (b < 48) {
        __shared__ float As[128], Bs[128];
        if (tid < 128) {
            float ss = 0.f, qq = 0.f;
            #pragma unroll 8
            for (int p = 0; p < 96; p++) {
                ss += g_xs_part[p * 128 + tid];
                qq += g_xq_part[p * 128 + tid];
            }
            const float invN = 1.0f / NN;
            float mean = ss * invN;
            float ex2  = qq * invN;
            float mm   = mean * nq_ms[tid];
            float var  = ex2 - 2.f * mm * mean + mm * mm;
            float rinv = rsqrtf(var + 1e-5f);
            As[tid] = nq_w[tid] * rinv;
            Bs[tid] = nq_b[tid] - nq_w[tid] * rinv * mm;
        }
        __syncthreads();
        int r0 = b * 128;
        const float4* xg = (const float4*)x;
        for (int i = tid; i < 128 * 32; i += 256) {
            int row = i >> 5, c4 = i & 31, c = c4 * 4;
            float4 v = xg[(size_t)(r0 + row) * 32 + c4];
            float f[4];
            f[0] = fmaf(v.x, As[c],     Bs[c]);
            f[1] = fmaf(v.y, As[c + 1], Bs[c + 1]);
            f[2] = fmaf(v.z, As[c + 2], Bs[c + 2]);
            f[3] = fmaf(v.w, As[c + 3], Bs[c + 3]);
            unsigned short h[4], l[4];
            #pragma unroll
            for (int j = 0; j < 4; j++) {
                h[j] = bf16bits(f[j]);
                l[j] = bf16bits(f[j] - bf16val(f[j]));
            }
            uint2 uh, ul;
            uh.x = (u32)h[0] | ((u32)h[1] << 16); uh.y = (u32)h[2] | ((u32)h[3] << 16);
            ul.x = (u32)l[0] | ((u32)l[1] << 16); ul.y = (u32)l[2] | ((u32)l[3] << 16);
            size_t idx = (size_t)(r0 + row) * 32 + c4;
            xh[idx] = uh; xl[idx] = ul;
        }
        // residual init: g_h = x[:, :64] + x[:, 64:]
        float4* h4 = (float4*)g_h;
        for (int i = tid; i < 128 * 16; i += 256) {
            int row = i >> 4, c4 = i & 15;
            float4 xa = xg[(size_t)(r0 + row) * 32 + c4];
            float4 xb = xg[(size_t)(r0 + row) * 32 + 16 + c4];
            h4[(size_t)(r0 + row) * 16 + c4] =
                make_float4(xa.x + xb.x, xa.y + xb.y, xa.z + xb.z, xa.w + xb.w);
        }
    } else {
        int wr0 = (b - 48) * 128;
        for (int i = tid; i < 128 * 32; i += 256) {
            int row = i >> 5, c4 = i & 31;
            int gidx = wr0 + row;
            int mat = gidx >> 9, lr = gidx & 511;
            const float4* src = (const float4*)(mat == 0 ? wq : (mat == 1 ? wk : wv));
            float4 v = src[(size_t)lr * 32 + c4];
            float f[4] = {v.x, v.y, v.z, v.w};
            unsigned short h[4], l[4];
            #pragma unroll
            for (int j = 0; j < 4; j++) {
                h[j] = bf16bits(f[j]);
                l[j] = bf16bits(f[j] - bf16val(f[j]));
            }
            uint2 uh, ul;
            uh.x = (u32)h[0] | ((u32)h[1] << 16); uh.y = (u32)h[2] | ((u32)h[3] << 16);
            ul.x = (u32)l[0] | ((u32)l[1] << 16); ul.y = (u32)l[2] | ((u32)l[3] << 16);
            size_t idx = (size_t)gidx * 32 + c4;
            wh[idx] = uh; wl[idx] = ul;
        }
    }
}

// ---------------- K3: QKV GEMM via mma.sync bf16 split (hi+lo) --------------
#define ROWB 272
#define ATILE (128 * ROWB)
#define BTILE (64 * ROWB)
__global__ void __launch_bounds__(256, 2)
k_qkv(const float* __restrict__ bq, const float* __restrict__ bk,
      const float* __restrict__ bv) {
    extern __shared__ char smc[];
    float* bias_s = (float*)smc;
    char* aH = smc + 512;
    char* aL = aH + ATILE;
    char* bH = aL + ATILE;
    char* bL = bH + BTILE;

    int tid = threadIdx.x;
    int m0 = blockIdx.x * 128;
    int oc = blockIdx.y * 64;
    int mat = oc >> 9, o0 = oc & 511;
    const float* bias = mat == 0 ? bq : (mat == 1 ? bk : bv);
    if (tid < 64) bias_s[tid] = bias[o0 + tid];

    const uint2* xh = (const uint2*)g_xhi;
    const uint2* xl = (const uint2*)g_xlo;
    const uint2* wh = (const uint2*)g_whi;
    const uint2* wl = (const uint2*)g_wlo;

    #pragma unroll
    for (int i = tid; i < 4096; i += 256) {
        int row = i >> 5, c4 = i & 31;
        int so = row * ROWB + c4 * 8;
        size_t ax = (size_t)(m0 + row) * 32 + c4;
        *(uint2*)(aH + so) = xh[ax];
        *(uint2*)(aL + so) = xl[ax];
    }
    #pragma unroll
    for (int i = tid; i < 2048; i += 256) {
        int row = i >> 5, c4 = i & 31;
        int so = row * ROWB + c4 * 8;
        size_t bx = (size_t)(oc + row) * 32 + c4;
        *(uint2*)(bH + so) = wh[bx];
        *(uint2*)(bL + so) = wl[bx];
    }
    __syncthreads();

    u32 sb = smem_u32(smc);
    u32 aHb = sb + 512, aLb = aHb + ATILE, bHb = aLb + ATILE, bLb = bHb + BTILE;

    int t   = tid & 31;
    int wid = tid >> 5;
    int wm = (wid & 3) * 32;
    int wn = (wid >> 2) * 32;
    int rowA = ((t >> 3) & 1) * 8 + (t & 7);
    int kofA = (t >> 4) * 8;
    int rowB = (t & 7);
    int kofB = ((t >> 3) & 1) * 8;

    float acc[2][4][4];
    #pragma unroll
    for (int mf = 0; mf < 2; mf++)
        #pragma unroll
        for (int nf = 0; nf < 4; nf++)
            #pragma unroll
            for (int j = 0; j < 4; j++) acc[mf][nf][j] = 0.f;

    for (int k = 0; k < 128; k += 16) {
        u32 ah[2][4], al[2][4], bh[4][2], bl[4][2];
        #pragma unroll
        for (int mf = 0; mf < 2; mf++) {
            u32 off = (u32)((wm + mf * 16 + rowA) * ROWB + (k + kofA) * 2);
            ldsm_x4(ah[mf][0], ah[mf][1], ah[mf][2], ah[mf][3], aHb + off);
            ldsm_x4(al[mf][0], al[mf][1], al[mf][2], al[mf][3], aLb + off);
        }
        #pragma unroll
        for (int nf = 0; nf < 4; nf++) {
            u32 off = (u32)((wn + nf * 8 + rowB) * ROWB + (k + kofB) * 2);
            ldsm_x2(bh[nf][0], bh[nf][1], bHb + off);
            ldsm_x2(bl[nf][0], bl[nf][1], bLb + off);
        }
        #pragma unroll
        for (int mf = 0; mf < 2; mf++)
            #pragma unroll
            for (int nf = 0; nf < 4; nf++) {
                mma_bf16(acc[mf][nf], ah[mf], bh[nf]);
                mma_bf16(acc[mf][nf], ah[mf], bl[nf]);
                mma_bf16(acc[mf][nf], al[mf], bh[nf]);
            }
    }

    int tq = t >> 2, tr = t & 3;
    #pragma unroll
    for (int mf = 0; mf < 2; mf++) {
        int m = m0 + wm + mf * 16 + tq;
        #pragma unroll
        for (int nf = 0; nf < 4; nf++) {
            int ln = wn + nf * 8 + tr * 2;
            float b0 = bias_s[ln], b1 = bias_s[ln + 1];
            *(__half2*)(g_qkv + (size_t)m * QKV_W + oc + ln) =
                __floats2half2_rn(acc[mf][nf][0] + b0, acc[mf][nf][1] + b1);
            *(__half2*)(g_qkv + (size_t)(m + 8) * QKV_W + oc + ln) =
                __floats2half2_rn(acc[mf][nf][2] + b0, acc[mf][nf][3] + b1);
        }
    }
}

// ---------------- K4: attention, 2 heads of one set per CTA (fp16 gmem) -----
#define PBUF 1192   // float4 units per head: q 408 | kt 400 | v 384
__global__ void __launch_bounds__(192, 5)
k_attn() {
    __shared__ float4 buf[2][PBUF];
    __shared__ __align__(16) float alphaT[2][24 * 24];   // [s][d]

    int tid = threadIdx.x;
    int set = blockIdx.x >> 2;
    int h0  = (blockIdx.x & 3) << 1;
    int n0  = set * G;

    // load both heads' q/k/v (fp16 gmem -> fp32 smem); 6 LDG.128 per thread
    const uint4* srcH = (const uint4*)g_qkv + (size_t)n0 * 192;  // 192 uint4/row
    #pragma unroll
    for (int p = 0; p < 2; p++) {
        int h = h0 + p;
        float4* q4h = buf[p];
        float4* kt4 = buf[p] + 408;
        float4* v4h = buf[p] + 808;
        int n = tid >> 3, g = tid & 7;           // 192 items exactly
        uint4 uq = srcH[n * 192 + h * 8 + g];
        uint4 uk = srcH[n * 192 + 64 + h * 8 + g];
        uint4 uv = srcH[n * 192 + 128 + h * 8 + g];
        float4 f0, f1;
        cvt8(uq, f0, f1);
        q4h[n * 17 + 2 * g] = f0; q4h[n * 17 + 2 * g + 1] = f1;
        cvt8(uk, f0, f1);
        kt4[(2 * g) * 25 + n] = f0; kt4[(2 * g + 1) * 25 + n] = f1;
        cvt8(uv, f0, f1);
        v4h[n * 16 + 2 * g] = f0; v4h[n * 16 + 2 * g + 1] = f1;
    }
    __syncthreads();

    // logits: 192 threads = 2 heads x 96 (each: 2 d x 3 s)
    {
        int p = tid >= 96;
        int r = tid - p * 96;
        const ulonglong2* q8 = (const ulonglong2*)buf[p];
        const ulonglong2* k8 = (const ulonglong2*)(buf[p] + 408);
        float* aT = alphaT[p];
        int d0 = (r >> 3) * 2;
        int sg = r & 7;
        u64 a00 = 0, a01 = 0, a02 = 0, a10 = 0, a11 = 0, a12 = 0;
        #pragma unroll
        for (int j = 0; j < 16; j++) {
            ulonglong2 q0 = q8[d0 * 17 + j];
            ulonglong2 q1 = q8[(d0 + 1) * 17 + j];
            ulonglong2 k0 = k8[j * 25 + sg * 3];
            ulonglong2 k1 = k8[j * 25 + sg * 3 + 1];
            ulonglong2 k2 = k8[j * 25 + sg * 3 + 2];
            a00 = fma2(q0.x, k0.x, a00); a00 = fma2(q0.y, k0.y, a00);
            a01 = fma2(q0.x, k1.x, a01); a01 = fma2(q0.y, k1.y, a01);
            a02 = fma2(q0.x, k2.x, a02); a02 = fma2(q0.y, k2.y, a02);
            a10 = fma2(q1.x, k0.x, a10); a10 = fma2(q1.y, k0.y, a10);
            a11 = fma2(q1.x, k1.x, a11); a11 = fma2(q1.y, k1.y, a11);
            a12 = fma2(q1.x, k2.x, a12); a12 = fma2(q1.y, k2.y, a12);
        }
        float lo, hi;
        int s0 = sg * 3;
        unpack2(a00, lo, hi); aT[(s0 + 0) * 24 + d0]     = (lo + hi) * 0.125f;
        unpack2(a01, lo, hi); aT[(s0 + 1) * 24 + d0]     = (lo + hi) * 0.125f;
        unpack2(a02, lo, hi); aT[(s0 + 2) * 24 + d0]     = (lo + hi) * 0.125f;
        unpack2(a10, lo, hi); aT[(s0 + 0) * 24 + d0 + 1] = (lo + hi) * 0.125f;
        unpack2(a11, lo, hi); aT[(s0 + 1) * 24 + d0 + 1] = (lo + hi) * 0.125f;
        unpack2(a12, lo, hi); aT[(s0 + 2) * 24 + d0 + 1] = (lo + hi) * 0.125f;
    }
    __syncthreads();

    // softmax: 48 threads = 2 heads x 24 destinations
    if (tid < 48) {
        int p = tid / 24, d = tid - p * 24;
        float* aT = alphaT[p];
        float m = aT[d];
        #pragma unroll
        for (int s = 1; s < G; s++) m = fmaxf(m, aT[s * 24 + d]);
        float sum = 0.f;
        #pragma unroll
        for (int s = 0; s < G; s++) {
            float e = expf(aT[s * 24 + d] - m);
            aT[s * 24 + d] = e;
            sum += e;
        }
        float inv = 1.0f / (sum + 1e-16f);
        #pragma unroll
        for (int s = 0; s < G; s++) aT[s * 24 + d] *= inv;
    }
    __syncthreads();

    // aggregate: 96 threads (dg, c4); both heads summed into the same accs
    if (tid < 96) {
        int dg = tid >> 4, c4 = tid & 15, d0 = dg * 4;
        u64 acc[4][2];
        #pragma unroll
        for (int i2 = 0; i2 < 4; i2++) { acc[i2][0] = 0ull; acc[i2][1] = 0ull; }
        #pragma unroll
        for (int p = 0; p < 2; p++) {
            const ulonglong2* v8 = (const ulonglong2*)(buf[p] + 808);
            const float* aT = alphaT[p];
            #pragma unroll
            for (int s = 0; s < G; s++) {
                float4 al = *(const float4*)&aT[s * 24 + d0];
                ulonglong2 vv = v8[s * 16 + c4];
                u64 pp;
                pp = pack2(al.x, al.x); acc[0][0] = fma2(pp, vv.x, acc[0][0]); acc[0][1] = fma2(pp, vv.y, acc[0][1]);
                pp = pack2(al.y, al.y); acc[1][0] = fma2(pp, vv.x, acc[1][0]); acc[1][1] = fma2(pp, vv.y, acc[1][1]);
                pp = pack2(al.z, al.z); acc[2][0] = fma2(pp, vv.x, acc[2][0]); acc[2][1] = fma2(pp, vv.y, acc[2][1]);
                pp = pack2(al.w, al.w); acc[3][0] = fma2(pp, vv.x, acc[3][0]); acc[3][1] = fma2(pp, vv.y, acc[3][1]);
            }
        }
        #pragma unroll
        for (int i2 = 0; i2 < 4; i2++) {
            float* dst = g_h + (size_t)(n0 + d0 + i2) * DH + c4 * 4;
            float x0, x1, x2, x3;
            unpack2(acc[i2][0], x0, x1);
            unpack2(acc[i2][1], x2, x3);
            atomicAdd(dst + 0, x0 * 0.125f);
            atomicAdd(dst + 1, x1 * 0.125f);
            atomicAdd(dst + 2, x2 * 0.125f);
            atomicAdd(dst + 3, x3 * 0.125f);
        }
    }
}

// ---------------- K5: h stats (96 blocks x 64 rows) -------------------------
__global__ void __launch_bounds__(256)
k_hstats() {
    __shared__ float smS[16 * 64], smQ[16 * 64];
    int t  = threadIdx.x;
    int c4 = t & 15;
    int rs = t >> 4;
    int r0 = blockIdx.x * 64;

    const float4* h4 = (const float4*)g_h;
    float4 s = make_float4(0.f, 0.f, 0.f, 0.f);
    float4 q = make_float4(0.f, 0.f, 0.f, 0.f);
    #pragma unroll
    for (int r = rs; r < 64; r += 16) {
        float4 a = h4[(size_t)(r0 + r) * 16 + c4];
        s.x += a.x; s.y += a.y; s.z += a.z; s.w += a.w;
        q.x += a.x * a.x; q.y += a.y * a.y; q.z += a.z * a.z; q.w += a.w * a.w;
    }
    ((float4*)smS)[rs * 16 + c4] = s;
    ((float4*)smQ)[rs * 16 + c4] = q;
    __syncthreads();
    if (t < 64) {
        float ss = 0.f, qq = 0.f;
        #pragma unroll
        for (int j = 0; j < 16; j++) { ss += smS[j * 64 + t]; qq += smQ[j * 64 + t]; }
        atomicAdd(&g_hsum[t], ss);
        atomicAdd(&g_hsumsq[t], qq);
    }
}

__device__ __forceinline__ float gelu_exact(float v) {
    return 0.5f * v * (1.0f + erff(v * 0.70710678118654752f));
}

// ---------------- K6: global norm + PFF + per-set norm + score + pooling ----
#define WPU 65
__global__ void __launch_bounds__(256)
k_final(const float* __restrict__ x,
        const float* __restrict__ no_w, const float* __restrict__ no_b,
        const float* __restrict__ no_ms,
        const float* __restrict__ o_w1, const float* __restrict__ o_b1,
        const float* __restrict__ o_w2, const float* __restrict__ o_b2,
        const float* __restrict__ pn_w, const float* __restrict__ pn_b,
        const float* __restrict__ pn_ms,
        const float* __restrict__ p_w1, const float* __restrict__ p_b1,
        const float* __restrict__ p_w2, const float* __restrict__ p_b2,
        float* __restrict__ out) {
    extern __shared__ float dsm[];
    u64*  w1P  = (u64*)dsm;
    u64*  w2P  = w1P + 32 * WPU;
    u64*  pw1P = w2P + 32 * WPU;
    u64*  pw2P = pw1P + 32 * WPU;
    float* hs  = (float*)(pw2P + 32);
    float* hn  = hs + G * DH;
    float* t1  = hn + G * DH;
    float* h2  = t1 + G * DH;
    float* a2  = h2 + G * DH;
    float* b2v = a2 + DH;
    float* cm  = b2v + DH;
    float* cr  = cm + DH;
    float* b1s = cr + DH;
    float* b2s = b1s + DH;
    float* pb1s = b2s + DH;
    float* score = pb1s + DH;
    float* wsf   = score + G;

    int tid = threadIdx.x;
    int n0  = blockIdx.x * G;

    for (int i = tid; i < 64 * 32; i += 256) {
        int j = i >> 5, c2 = i & 31;
        float2 w1v = *(const float2*)(o_w1 + j * 64 + c2 * 2);
        w1P[c2 * WPU + j] = pack2(w1v.x, w1v.y);
        float2 pw = *(const float2*)(p_w1 + j * 64 + c2 * 2);
        pw1P[c2 * WPU + j] = pack2(pw.x, pw.y);
        float2 w2v = *(const float2*)(o_w2 + j * 64 + c2 * 2);
        w2P[c2 * WPU + j] = pack2(w2v.x, w2v.y);
    }
    if (tid < 32) {
        pw2P[tid] = pack2(p_w2[tid * 2], p_w2[tid * 2 + 1]);
    }
    if (tid < DH) {
        b1s[tid] = o_b1[tid]; b2s[tid] = o_b2[tid];
        pb1s[tid] = p_b1[tid];
        const float invN = 1.0f / NN;
        float mean = g_hsum[tid] * invN;
        float ex2  = g_hsumsq[tid] * invN;
        float mm   = mean * no_ms[tid];
        float var  = ex2 - 2.f * mm * mean + mm * mm;
        float rinv = rsqrtf(var + 1e-5f);
        a2[tid] = no_w[tid] * rinv;
        b2v[tid] = no_b[tid] - no_w[tid] * rinv * mm;
    }
    for (int i = tid; i < G * DH; i += 256) hs[i] = g_h[(size_t)n0 * DH + i];
    __syncthreads();

    for (int i = tid; i < G * DH; i += 256) {
        int c = i & 63;
        hn[i] = fmaf(hs[i], a2[c], b2v[c]);
    }
    __syncthreads();

    for (int i = tid; i < 384; i += 256) {
        int dp = i >> 5, jp = i & 31, d0 = dp * 2;
        u64 A00 = 0, A01 = 0, A10 = 0, A11 = 0;
        const u64* h0 = (const u64*)(hn + d0 * DH);
        const u64* h1 = (const u64*)(hn + (d0 + 1) * DH);
        #pragma unroll 8
        for (int c2 = 0; c2 < 32; c2++) {
            u64 w0 = w1P[c2 * WPU + jp], w1 = w1P[c2 * WPU + jp + 32];
            u64 hc0 = h0[c2], hc1 = h1[c2];
            A00 = fma2(hc0, w0, A00); A01 = fma2(hc0, w1, A01);
            A10 = fma2(hc1, w0, A10); A11 = fma2(hc1, w1, A11);
        }
        float lo, hi;
        unpack2(A00, lo, hi); t1[d0 * DH + jp]            = gelu_exact(lo + hi + b1s[jp]);
        unpack2(A01, lo, hi); t1[d0 * DH + jp + 32]       = gelu_exact(lo + hi + b1s[jp + 32]);
        unpack2(A10, lo, hi); t1[(d0 + 1) * DH + jp]      = gelu_exact(lo + hi + b1s[jp]);
        unpack2(A11, lo, hi); t1[(d0 + 1) * DH + jp + 32] = gelu_exact(lo + hi + b1s[jp + 32]);
    }
    __syncthreads();

    for (int i = tid; i < 384; i += 256) {
        int dp = i >> 5, cp = i & 31, d0 = dp * 2;
        u64 A00 = 0, A01 = 0, A10 = 0, A11 = 0;
        const u64* t0 = (const u64*)(t1 + d0 * DH);
        const u64* t1r = (const u64*)(t1 + (d0 + 1) * DH);
        #pragma unroll 8
        for (int j2 = 0; j2 < 32; j2++) {
            u64 w0 = w2P[j2 * WPU + cp], w1 = w2P[j2 * WPU + cp + 32];
            u64 tc0 = t0[j2], tc1 = t1r[j2];
            A00 = fma2(tc0, w0, A00); A01 = fma2(tc0, w1, A01);
            A10 = fma2(tc1, w0, A10); A11 = fma2(tc1, w1, A11);
        }
        float lo, hi;
        unpack2(A00, lo, hi); h2[d0 * DH + cp]            = hs[d0 * DH + cp] + lo + hi + b2s[cp];
        unpack2(A01, lo, hi); h2[d0 * DH + cp + 32]       = hs[d0 * DH + cp + 32] + lo + hi + b2s[cp + 32];
        unpack2(A10, lo, hi); h2[(d0 + 1) * DH + cp]      = hs[(d0 + 1) * DH + cp] + lo + hi + b2s[cp];
        unpack2(A11, lo, hi); h2[(d0 + 1) * DH + cp + 32] = hs[(d0 + 1) * DH + cp + 32] + lo + hi + b2s[cp + 32];
    }
    __syncthreads();

    if (tid < DH) {
        int c = tid;
        float m = 0.f;
        #pragma unroll
        for (int d = 0; d < G; d++) m += h2[d * DH + c];
        m *= (1.0f / G);
        float mm = m * pn_ms[c];
        float vv = 0.f;
        #pragma unroll
        for (int d = 0; d < G; d++) { float t = h2[d * DH + c] - mm; vv += t * t; }
        vv *= (1.0f / G);
        cm[c] = mm;
        cr[c] = pn_w[c] * rsqrtf(vv + 1e-5f);
    }
    __syncthreads();

    for (int i = tid; i < G * DH; i += 256) {
        int c = i & 63;
        hn[i] = fmaf(h2[i] - cm[c], cr[c], pn_b[c]);
    }
    __syncthreads();

    for (int i = tid; i < 384; i += 256) {
        int dp = i >> 5, jp = i & 31, d0 = dp * 2;
        u64 A00 = 0, A01 = 0, A10 = 0, A11 = 0;
        const u64* h0 = (const u64*)(hn + d0 * DH);
        const u64* h1 = (const u64*)(hn + (d0 + 1) * DH);
        #pragma unroll 8
        for (int c2 = 0; c2 < 32; c2++) {
            u64 w0 = pw1P[c2 * WPU + jp], w1 = pw1P[c2 * WPU + jp + 32];
            u64 hc0 = h0[c2], hc1 = h1[c2];
            A00 = fma2(hc0, w0, A00); A01 = fma2(hc0, w1, A01);
            A10 = fma2(hc1, w0, A10); A11 = fma2(hc1, w1, A11);
        }
        float lo, hi;
        unpack2(A00, lo, hi); t1[d0 * DH + jp]            = gelu_exact(lo + hi + pb1s[jp]);
        unpack2(A01, lo, hi); t1[d0 * DH + jp + 32]       = gelu_exact(lo + hi + pb1s[jp + 32]);
        unpack2(A10, lo, hi); t1[(d0 + 1) * DH + jp]      = gelu_exact(lo + hi + pb1s[jp]);
        unpack2(A11, lo, hi); t1[(d0 + 1) * DH + jp + 32] = gelu_exact(lo + hi + pb1s[jp + 32]);
    }
    __syncthreads();

    if (tid < G) {
        const u64* tr = (const u64*)(t1 + tid * DH);
        u64 A = 0;
        #pragma unroll 8
        for (int j2 = 0; j2 < 32; j2++) A = fma2(tr[j2], pw2P[j2], A);
        float lo, hi;
        unpack2(A, lo, hi);
        score[tid] = lo + hi + p_b2[0];
    }
    __syncthreads();

    if (tid == 0) {
        float m = score[0];
        #pragma unroll
        for (int d = 1; d < G; d++) m = fmaxf(m, score[d]);
        float sum = 0.f;
        #pragma unroll
        for (int d = 0; d < G; d++) { wsf[d] = expf(score[d] - m); sum += wsf[d]; }
        float inv = 1.0f / (sum + 1e-16f);
        #pragma unroll
        for (int d = 0; d < G; d++) wsf[d] *= inv;
    }
    __syncthreads();

    if (tid < DIN) {
        float acc = 0.f;
        #pragma unroll
        for (int d = 0; d < G; d++)
            acc = fmaf(wsf[d], x[(size_t)(n0 + d) * DIN + tid], acc);
        out[blockIdx.x * DIN + tid] = acc;
    }
}

// ---------------- launch -----------------------------------------------------
extern "C" void kernel_launch(void* const* d_in, const int* in_sizes, int n_in,
                              void* d_out, int out_size) {
    const float* x     = (const float*)d_in[0];
    const float* nq_w  = (const float*)d_in[4];
    const float* nq_b  = (const float*)d_in[5];
    const float* nq_ms = (const float*)d_in[6];
    const float* wq    = (const float*)d_in[7];
    const float* bq    = (const float*)d_in[8];
    const float* wk    = (const float*)d_in[9];
    const float* bk    = (const float*)d_in[10];
    const float* wv    = (const float*)d_in[11];
    const float* bv    = (const float*)d_in[12];
    const float* no_w  = (const float*)d_in[13];
    const float* no_b  = (const float*)d_in[14];
    const float* no_ms = (const float*)d_in[15];
    const float* o_w1  = (const float*)d_in[16];
    const float* o_b1  = (const float*)d_in[17];
    const float* o_w2  = (const float*)d_in[18];
    const float* o_b2  = (const float*)d_in[19];
    const float* pn_w  = (const float*)d_in[20];
    const float* pn_b  = (const float*)d_in[21];
    const float* pn_ms = (const float*)d_in[22];
    const float* p_w1  = (const float*)d_in[23];
    const float* p_b1  = (const float*)d_in[24];
    const float* p_w2  = (const float*)d_in[25];
    const float* p_b2  = (const float*)d_in[26];
    float* out = (float*)d_out;

    const int smem_qkv = 512 + 2 * ATILE + 2 * BTILE;
    const int smem_fin = (3 * 32 * WPU + 32) * 8 + (4 * G * DH + 7 * DH + 2 * G) * 4;
    cudaFuncSetAttribute(k_qkv,   cudaFuncAttributeMaxDynamicSharedMemorySize, smem_qkv);
    cudaFuncSetAttribute(k_final, cudaFuncAttributeMaxDynamicSharedMemorySize, smem_fin);

    k_xstats<<<96, 256>>>(x);
    k_xnorm<<<60, 256>>>(x, nq_w, nq_b, nq_ms, wq, wk, wv);
    k_qkv<<<dim3(48, 24), 256, smem_qkv>>>(bq, bk, bv);
    k_attn<<<1024, 192>>>();
    k_hstats<<<96, 256>>>();
    k_final<<<256, 256, smem_fin>>>(x, no_w, no_b, no_ms,
                                    o_w1, o_b1, o_w2, o_b2,
                                    pn_w, pn_b, pn_ms,
                                    p_w1, p_b1, p_w2, p_b2, out);
}